// round 1
// baseline (speedup 1.0000x reference)
#include <cuda_runtime.h>
#include <cuda_bf16.h>
#include <math.h>

// Problem constants (fixed by the dataset)
#define NUM_POINTS 500000
#define NUM_SUP    8192
#define DEGREE     32
#define NUM_EDGES  (NUM_SUP * DEGREE)   // 262144
#define HIDDEN     256

// Edge kernel tiling
#define BLK_E      128                  // edges per block (4 supernodes)
#define XT_STRIDE  132                  // padded row stride (floats), 16B aligned
#define KCHUNK     32

// log(10000)/32, log(10000)/42
#define OM4_C 0.2878231366242559f
#define OM3_C 0.2192938183803854f

// 8 MB scratch for aggregated supernode features
__device__ float g_agg[NUM_SUP * HIDDEN];

// ---------------------------------------------------------------------------
// Kernel 1: per 128-edge tile:
//   rel = [dst-src, |dst-src|] ; X = sincos embed (E x 256)
//   H = gelu(X@W1+b1) ; Y = H@W2+b2 ; agg[s] = mean over 32 edges
// ---------------------------------------------------------------------------
__global__ __launch_bounds__(256, 1)
void edge_mlp_kernel(const float* __restrict__ pos,
                     const int* __restrict__ sup_idx,
                     const int* __restrict__ src_idx,
                     const float* __restrict__ w1, const float* __restrict__ b1,
                     const float* __restrict__ w2, const float* __restrict__ b2)
{
    extern __shared__ float sm[];
    float* Xt   = sm;                        // [256][XT_STRIDE] transposed tile
    float* Wb   = Xt + 256 * XT_STRIDE;      // [32][256] weight chunk
    float* relb = Wb + KCHUNK * 256;         // [128][4]

    const int tid = threadIdx.x;
    const int e0  = blockIdx.x * BLK_E;

    // ---- relative position per edge -------------------------------------
    if (tid < BLK_E) {
        int e  = e0 + tid;
        int s  = e >> 5;                     // dst_seg = e / DEGREE
        int si = sup_idx[s];
        int sr = src_idx[e];
        float dx = pos[si * 3 + 0] - pos[sr * 3 + 0];
        float dy = pos[si * 3 + 1] - pos[sr * 3 + 1];
        float dz = pos[si * 3 + 2] - pos[sr * 3 + 2];
        relb[tid * 4 + 0] = dx;
        relb[tid * 4 + 1] = dy;
        relb[tid * 4 + 2] = dz;
        relb[tid * 4 + 3] = sqrtf(dx * dx + dy * dy + dz * dz);
    }
    __syncthreads();

    // ---- sincos embedding, written transposed: Xt[k][r] ------------------
    {
        int k  = tid;                        // column 0..255
        int d  = k >> 6;                     // which of the 4 rel coords
        int j  = k & 63;
        int jj = j & 31;
        bool is_sin = (j < 32);
        float om = expf(-(float)jj * OM4_C); // 10000^{-jj/32}
        #pragma unroll 4
        for (int r = 0; r < BLK_E; r++) {
            float v = relb[r * 4 + d] * om;
            Xt[k * XT_STRIDE + r] = is_sin ? sinf(v) : cosf(v);
        }
    }

    const int tx = tid & 15;                 // 16 column groups
    const int ty = tid >> 4;                 // 16 row groups
    const int r0 = ty * 8;

    float bias1[16], bias2[16];
    #pragma unroll
    for (int g = 0; g < 4; g++)
        #pragma unroll
        for (int u = 0; u < 4; u++) {
            int c = tx * 4 + g * 64 + u;
            bias1[g * 4 + u] = b1[c];
            bias2[g * 4 + u] = b2[c];
        }

    float acc[8][16];

    // ================= GEMM 1: X @ W1 =====================================
    #pragma unroll
    for (int i = 0; i < 8; i++)
        #pragma unroll
        for (int j = 0; j < 16; j++) acc[i][j] = 0.0f;

    for (int kt = 0; kt < 256 / KCHUNK; kt++) {
        __syncthreads();
        {
            const float4* src = (const float4*)(w1 + kt * KCHUNK * 256);
            float4* dst = (float4*)Wb;
            #pragma unroll
            for (int i = 0; i < 8; i++) dst[i * 256 + tid] = src[i * 256 + tid];
        }
        __syncthreads();
        #pragma unroll 8
        for (int kk = 0; kk < KCHUNK; kk++) {
            int k = kt * KCHUNK + kk;
            float4 a0 = *(const float4*)&Xt[k * XT_STRIDE + r0];
            float4 a1 = *(const float4*)&Xt[k * XT_STRIDE + r0 + 4];
            float a[8] = {a0.x, a0.y, a0.z, a0.w, a1.x, a1.y, a1.z, a1.w};
            float b[16];
            #pragma unroll
            for (int g = 0; g < 4; g++) {
                float4 bb = *(const float4*)&Wb[kk * 256 + tx * 4 + g * 64];
                b[g * 4 + 0] = bb.x; b[g * 4 + 1] = bb.y;
                b[g * 4 + 2] = bb.z; b[g * 4 + 3] = bb.w;
            }
            #pragma unroll
            for (int i = 0; i < 8; i++)
                #pragma unroll
                for (int j = 0; j < 16; j++) acc[i][j] += a[i] * b[j];
        }
    }

    // ---- bias + exact GELU, store H transposed back into Xt --------------
    __syncthreads();
    #pragma unroll
    for (int i = 0; i < 8; i++)
        #pragma unroll
        for (int g = 0; g < 4; g++)
            #pragma unroll
            for (int u = 0; u < 4; u++) {
                int c = tx * 4 + g * 64 + u;
                float h = acc[i][g * 4 + u] + bias1[g * 4 + u];
                h = 0.5f * h * (1.0f + erff(h * 0.70710678118654752f));
                Xt[c * XT_STRIDE + r0 + i] = h;
            }
    __syncthreads();

    // ================= GEMM 2: H @ W2 =====================================
    #pragma unroll
    for (int i = 0; i < 8; i++)
        #pragma unroll
        for (int j = 0; j < 16; j++) acc[i][j] = 0.0f;

    for (int kt = 0; kt < 256 / KCHUNK; kt++) {
        __syncthreads();
        {
            const float4* src = (const float4*)(w2 + kt * KCHUNK * 256);
            float4* dst = (float4*)Wb;
            #pragma unroll
            for (int i = 0; i < 8; i++) dst[i * 256 + tid] = src[i * 256 + tid];
        }
        __syncthreads();
        #pragma unroll 8
        for (int kk = 0; kk < KCHUNK; kk++) {
            int k = kt * KCHUNK + kk;
            float4 a0 = *(const float4*)&Xt[k * XT_STRIDE + r0];
            float4 a1 = *(const float4*)&Xt[k * XT_STRIDE + r0 + 4];
            float a[8] = {a0.x, a0.y, a0.z, a0.w, a1.x, a1.y, a1.z, a1.w};
            float b[16];
            #pragma unroll
            for (int g = 0; g < 4; g++) {
                float4 bb = *(const float4*)&Wb[kk * 256 + tx * 4 + g * 64];
                b[g * 4 + 0] = bb.x; b[g * 4 + 1] = bb.y;
                b[g * 4 + 2] = bb.z; b[g * 4 + 3] = bb.w;
            }
            #pragma unroll
            for (int i = 0; i < 8; i++)
                #pragma unroll
                for (int j = 0; j < 16; j++) acc[i][j] += a[i] * b[j];
        }
    }

    // ---- bias, store Y transposed into Xt, then segment mean -------------
    __syncthreads();
    #pragma unroll
    for (int i = 0; i < 8; i++)
        #pragma unroll
        for (int g = 0; g < 4; g++)
            #pragma unroll
            for (int u = 0; u < 4; u++) {
                int c = tx * 4 + g * 64 + u;
                Xt[c * XT_STRIDE + r0 + i] = acc[i][g * 4 + u] + bias2[g * 4 + u];
            }
    __syncthreads();

    // 4 supernodes x 256 cols = 1024 outputs; thread handles (sl=t, c=tid)
    #pragma unroll
    for (int t = 0; t < 4; t++) {
        int c = tid;
        float s = 0.0f;
        #pragma unroll 8
        for (int r = t * 32; r < t * 32 + 32; r++) s += Xt[c * XT_STRIDE + r];
        g_agg[(blockIdx.x * 4 + t) * HIDDEN + c] = s * (1.0f / 32.0f);
    }
}

// ---------------------------------------------------------------------------
// Kernel 2: out = concat([agg, sincos(sup_pos)]) @ wp + bp
//   block: 64 supernodes x 256 cols, K = 512
// ---------------------------------------------------------------------------
#define BLK_S     64
#define AT_STRIDE 68

__global__ __launch_bounds__(256, 1)
void out_proj_kernel(const float* __restrict__ pos,
                     const int* __restrict__ sup_idx,
                     const float* __restrict__ wp, const float* __restrict__ bp,
                     float* __restrict__ out)
{
    extern __shared__ float sm[];
    float* At   = sm;                       // [512][AT_STRIDE]
    float* Wb   = At + 512 * AT_STRIDE;     // [32][256]
    float* spos = Wb + KCHUNK * 256;        // [64][3]

    const int tid = threadIdx.x;
    const int s0  = blockIdx.x * BLK_S;

    // agg rows: k = tid (0..255)
    #pragma unroll 4
    for (int r = 0; r < BLK_S; r++)
        At[tid * AT_STRIDE + r] = g_agg[(s0 + r) * HIDDEN + tid];

    if (tid < BLK_S) {
        int si = sup_idx[s0 + tid];
        spos[tid * 3 + 0] = pos[si * 3 + 0];
        spos[tid * 3 + 1] = pos[si * 3 + 1];
        spos[tid * 3 + 2] = pos[si * 3 + 2];
    }
    // zero-pad embedding columns 252..255 -> At rows 508..511
    {
        int k = 508 + (tid >> 6);
        int r = tid & 63;
        At[k * AT_STRIDE + r] = 0.0f;
    }
    __syncthreads();

    // sincos abs-pos embedding: 64 rows x 252 cols
    for (int idx = tid; idx < BLK_S * 252; idx += 256) {
        int r  = idx / 252;
        int kk = idx - r * 252;
        int d  = kk / 84;
        int j  = kk - d * 84;
        int jj = (j < 42) ? j : (j - 42);
        float om = expf(-(float)jj * OM3_C);   // 10000^{-jj/42}
        float v  = spos[r * 3 + d] * om;
        At[(256 + kk) * AT_STRIDE + r] = (j < 42) ? sinf(v) : cosf(v);
    }

    const int tx = tid & 31;                 // 32 column groups (8 cols each)
    const int ty = tid >> 5;                 // 8 row groups
    const int r0 = ty * 8;

    float biasv[8];
    #pragma unroll
    for (int g = 0; g < 2; g++)
        #pragma unroll
        for (int u = 0; u < 4; u++) biasv[g * 4 + u] = bp[tx * 4 + g * 128 + u];

    float acc[8][8];
    #pragma unroll
    for (int i = 0; i < 8; i++)
        #pragma unroll
        for (int j = 0; j < 8; j++) acc[i][j] = 0.0f;

    for (int kt = 0; kt < 512 / KCHUNK; kt++) {
        __syncthreads();
        {
            const float4* src = (const float4*)(wp + kt * KCHUNK * 256);
            float4* dst = (float4*)Wb;
            #pragma unroll
            for (int i = 0; i < 8; i++) dst[i * 256 + tid] = src[i * 256 + tid];
        }
        __syncthreads();
        #pragma unroll 8
        for (int kk = 0; kk < KCHUNK; kk++) {
            int k = kt * KCHUNK + kk;
            float4 a0 = *(const float4*)&At[k * AT_STRIDE + r0];
            float4 a1 = *(const float4*)&At[k * AT_STRIDE + r0 + 4];
            float a[8] = {a0.x, a0.y, a0.z, a0.w, a1.x, a1.y, a1.z, a1.w};
            float b[8];
            #pragma unroll
            for (int g = 0; g < 2; g++) {
                float4 bb = *(const float4*)&Wb[kk * 256 + tx * 4 + g * 128];
                b[g * 4 + 0] = bb.x; b[g * 4 + 1] = bb.y;
                b[g * 4 + 2] = bb.z; b[g * 4 + 3] = bb.w;
            }
            #pragma unroll
            for (int i = 0; i < 8; i++)
                #pragma unroll
                for (int j = 0; j < 8; j++) acc[i][j] += a[i] * b[j];
        }
    }

    // store: float4 per (row, colgroup); fully coalesced
    #pragma unroll
    for (int i = 0; i < 8; i++)
        #pragma unroll
        for (int g = 0; g < 2; g++) {
            float4 v;
            v.x = acc[i][g * 4 + 0] + biasv[g * 4 + 0];
            v.y = acc[i][g * 4 + 1] + biasv[g * 4 + 1];
            v.z = acc[i][g * 4 + 2] + biasv[g * 4 + 2];
            v.w = acc[i][g * 4 + 3] + biasv[g * 4 + 3];
            *(float4*)&out[(size_t)(s0 + r0 + i) * HIDDEN + tx * 4 + g * 128] = v;
        }
}

// ---------------------------------------------------------------------------
extern "C" void kernel_launch(void* const* d_in, const int* in_sizes, int n_in,
                              void* d_out, int out_size)
{
    const float* pos     = (const float*)d_in[0];   // (500000, 3)
    const int*   sup_idx = (const int*)d_in[1];     // (8192,)
    const int*   src_idx = (const int*)d_in[2];     // (262144,)
    // d_in[3] = dst_seg (implied by e/32)
    const float* w1 = (const float*)d_in[4];
    const float* b1 = (const float*)d_in[5];
    const float* w2 = (const float*)d_in[6];
    const float* b2 = (const float*)d_in[7];
    const float* wp = (const float*)d_in[8];
    const float* bp = (const float*)d_in[9];
    float* out = (float*)d_out;

    const int smem1 = (256 * XT_STRIDE + KCHUNK * 256 + BLK_E * 4) * 4;
    const int smem2 = (512 * AT_STRIDE + KCHUNK * 256 + BLK_S * 3) * 4;
    cudaFuncSetAttribute(edge_mlp_kernel,
                         cudaFuncAttributeMaxDynamicSharedMemorySize, smem1);
    cudaFuncSetAttribute(out_proj_kernel,
                         cudaFuncAttributeMaxDynamicSharedMemorySize, smem2);

    edge_mlp_kernel<<<NUM_EDGES / BLK_E, 256, smem1>>>(
        pos, sup_idx, src_idx, w1, b1, w2, b2);
    out_proj_kernel<<<NUM_SUP / BLK_S, 256, smem2>>>(
        pos, sup_idx, wp, bp, out);
}

// round 3
// speedup vs baseline: 2.4217x; 2.4217x over previous
#include <cuda_runtime.h>
#include <cuda_fp16.h>
#include <math.h>
#include <stdint.h>

#define NUM_POINTS 500000
#define NUM_SUP    8192
#define DEGREE     32
#define NUM_EDGES  (NUM_SUP * DEGREE)   // 262144
#define HIDDEN     256

#define OM4_C 0.2878231366242559f   // ln(10000)/32
#define OM3_C 0.2192938183803854f   // ln(10000)/42

// ---------------- global scratch ----------------
__device__ float g_agg[NUM_SUP * HIDDEN];
// weight chunks: [8 kchunks][2 terms(hi,lo)][256 n][40 k-padded] half
#define CHUNK_HALFS (2 * 256 * 40)            // 20480 half = 40960 B
__device__ __align__(256) __half g_w1c[8 * CHUNK_HALFS];
__device__ __align__(256) __half g_w2c[8 * CHUNK_HALFS];

// ---------------- edge-kernel smem layout (bytes) ----------------
#define A_STRIDE  264                          // halfs per row (256 + 8 pad)
#define AHI_OFF   0                            // 128 x 264 half = 67584 B
#define ALO_OFF   67584
#define BST_OFF   135168                       // 2 stages x 40960 B
#define REL_OFF   217088                       // 128 x 4 float
#define B1S_OFF   219136                       // 256 float
#define B2S_OFF   220160                       // 256 float
#define SMEM_EDGE 221184

// ---------------- PTX helpers ----------------
__device__ __forceinline__ uint32_t smem_u32(const void* p) {
    uint32_t a;
    asm("{ .reg .u64 t; cvta.to.shared.u64 t, %1; cvt.u32.u64 %0, t; }" : "=r"(a) : "l"(p));
    return a;
}
__device__ __forceinline__ void ldm_x4(uint32_t* r, uint32_t addr) {
    asm volatile("ldmatrix.sync.aligned.m8n8.x4.shared.b16 {%0,%1,%2,%3}, [%4];"
                 : "=r"(r[0]), "=r"(r[1]), "=r"(r[2]), "=r"(r[3]) : "r"(addr));
}
__device__ __forceinline__ void ldm_x2(uint32_t* r, uint32_t addr) {
    asm volatile("ldmatrix.sync.aligned.m8n8.x2.shared.b16 {%0,%1}, [%2];"
                 : "=r"(r[0]), "=r"(r[1]) : "r"(addr));
}
__device__ __forceinline__ void mma16816(float* d, const uint32_t* a, const uint32_t* b) {
    asm volatile("mma.sync.aligned.m16n8k16.row.col.f32.f16.f16.f32 "
                 "{%0,%1,%2,%3}, {%4,%5,%6,%7}, {%8,%9}, {%0,%1,%2,%3};"
                 : "+f"(d[0]), "+f"(d[1]), "+f"(d[2]), "+f"(d[3])
                 : "r"(a[0]), "r"(a[1]), "r"(a[2]), "r"(a[3]), "r"(b[0]), "r"(b[1]));
}
__device__ __forceinline__ void cp16(uint32_t dst, const void* src) {
    asm volatile("cp.async.cg.shared.global [%0], [%1], 16;" :: "r"(dst), "l"(src) : "memory");
}
#define CP_COMMIT() asm volatile("cp.async.commit_group;" ::: "memory")
#define CP_WAIT1()  asm volatile("cp.async.wait_group 1;" ::: "memory")
#define CP_WAIT0()  asm volatile("cp.async.wait_group 0;" ::: "memory")

// store hi/lo fp16 split of (x, y) at A[m][c], A[m][c+1]  (c even)
__device__ __forceinline__ void storeA(char* smc, int m, int c, float x, float y) {
    __half hx = __float2half_rn(x);
    __half hy = __float2half_rn(y);
    float lx = x - __half2float(hx);
    float ly = y - __half2float(hy);
    uint32_t off = (uint32_t)(m * A_STRIDE + c) * 2;
    *(__half2*)(smc + AHI_OFF + off) = __halves2half2(hx, hy);
    *(__half2*)(smc + ALO_OFF + off) = __halves2half2(__float2half_rn(lx), __float2half_rn(ly));
}

// fill one 40960 B weight stage (256 threads x 10 x 16 B)
__device__ __forceinline__ void fill_stage(uint32_t dst_sb, const __half* src, int tid) {
    const char* g = (const char*)src + tid * 16;
    uint32_t d = dst_sb + tid * 16;
    #pragma unroll
    for (int i = 0; i < 10; i++) cp16(d + i * 4096, g + i * 4096);
}

// ---------------------------------------------------------------------------
// prep: split w[k][n] (fp32 row-major) into hi/lo fp16, transposed to n-major,
// padded chunk layout [kc][term][n][40] — runtime streaming is a raw memcpy.
// ---------------------------------------------------------------------------
__global__ void prep_weights(const float* __restrict__ w1, const float* __restrict__ w2) {
    int idx = blockIdx.x * blockDim.x + threadIdx.x;   // 131072
    const float* w = (idx < 65536) ? w1 : w2;
    __half* dst = (idx < 65536) ? g_w1c : g_w2c;
    int i = idx & 65535;
    int k = i >> 8, n = i & 255;
    float v = w[i];
    __half hi = __float2half_rn(v);
    float lo = v - __half2float(hi);
    int kc = k >> 5, kk = k & 31;
    dst[(size_t)kc * CHUNK_HALFS + (0 * 256 + n) * 40 + kk] = hi;
    dst[(size_t)kc * CHUNK_HALFS + (1 * 256 + n) * 40 + kk] = __float2half_rn(lo);
}

// ---------------------------------------------------------------------------
// Edge kernel: 128 edges/CTA, HMMA split GEMMs, fused GELU + segment mean.
// ---------------------------------------------------------------------------
__global__ __launch_bounds__(256, 1)
void edge_mlp_mma(const float* __restrict__ pos,
                  const int* __restrict__ sup_idx,
                  const int* __restrict__ src_idx,
                  const float* __restrict__ b1,
                  const float* __restrict__ b2) {
    extern __shared__ char smc[];
    const uint32_t sb = smem_u32(smc);
    const int tid  = threadIdx.x;
    const int wid  = tid >> 5;
    const int lane = tid & 31;
    const int mg   = wid & 3;     // M-group: rows [mg*32, mg*32+32) = supernode mg
    const int ng   = wid >> 2;    // N-group: cols [ng*128, ng*128+128)

    float* b1s = (float*)(smc + B1S_OFF);
    float* b2s = (float*)(smc + B2S_OFF);
    b1s[tid] = b1[tid];
    b2s[tid] = b2[tid];

    // prefetch first two weight chunks
    fill_stage(sb + BST_OFF,         g_w1c,               tid); CP_COMMIT();
    fill_stage(sb + BST_OFF + 40960, g_w1c + CHUNK_HALFS, tid); CP_COMMIT();

    // ---- relative positions ----
    if (tid < 128) {
        int e = blockIdx.x * 128 + tid;
        int si = sup_idx[e >> 5], sr = src_idx[e];
        float dx = pos[si * 3 + 0] - pos[sr * 3 + 0];
        float dy = pos[si * 3 + 1] - pos[sr * 3 + 1];
        float dz = pos[si * 3 + 2] - pos[sr * 3 + 2];
        float* rb = (float*)(smc + REL_OFF);
        rb[tid * 4 + 0] = dx; rb[tid * 4 + 1] = dy; rb[tid * 4 + 2] = dz;
        rb[tid * 4 + 3] = sqrtf(dx * dx + dy * dy + dz * dz);
    }
    __syncthreads();

    // ---- sincos embed -> A hi/lo (thread: row m=tid&127, col half h) ----
    {
        const float* rb = (const float*)(smc + REL_OFF);
        int m = tid & 127, h = tid >> 7;
        float r2 = rb[m * 4 + h * 2], r3 = rb[m * 4 + h * 2 + 1];
        // cols h*128 .. h*128+127  => d in {2h, 2h+1}
        #pragma unroll 4
        for (int j = 0; j < 64; j += 2) {
            int jj = j & 31;
            float om0 = __expf(-(float)jj * OM4_C);
            float om1 = __expf(-(float)(jj + 1) * OM4_C);
            float a0 = r2 * om0, a1 = r2 * om1;
            float c0 = r3 * om0, c1 = r3 * om1;
            if (j < 32) {
                storeA(smc, m, (h * 2) * 64 + j,       __sinf(a0), __sinf(a1));
                storeA(smc, m, (h * 2 + 1) * 64 + j,   __sinf(c0), __sinf(c1));
            } else {
                storeA(smc, m, (h * 2) * 64 + j,       __cosf(a0), __cosf(a1));
                storeA(smc, m, (h * 2 + 1) * 64 + j,   __cosf(c0), __cosf(c1));
            }
        }
    }
    __syncthreads();   // A ready for all warps

    float acc[2][16][4];
    #pragma unroll
    for (int t = 0; t < 2; t++)
        #pragma unroll
        for (int j = 0; j < 16; j++)
            #pragma unroll
            for (int q = 0; q < 4; q++) acc[t][j][q] = 0.0f;

    // lane-dependent bases
    const uint32_t a_row  = (uint32_t)(mg * 32 + (lane & 15));
    const uint32_t a_koff = (uint32_t)((lane >> 4) * 8);
    const uint32_t b_base = sb + BST_OFF +
        (uint32_t)(((ng * 128 + (lane & 7)) * 40 + ((lane >> 3) & 1) * 8) * 2);

    const int l4 = lane >> 2;
    const int l2 = (lane & 3) * 2;

    #pragma unroll 1
    for (int c = 0; c < 16; c++) {
        const int buf = c & 1;
        const int kc  = c & 7;
        if (c < 15) { CP_WAIT1(); } else { CP_WAIT0(); }
        __syncthreads();   // stage[buf] visible to all

        if (c == 8) {
            // ---- epilogue 1: bias + exact GELU -> rewrite A hi/lo ----
            #pragma unroll
            for (int t = 0; t < 2; t++)
                #pragma unroll
                for (int j = 0; j < 16; j++) {
                    int r  = mg * 32 + t * 16 + l4;
                    int cc = ng * 128 + j * 8 + l2;
                    float v0 = acc[t][j][0] + b1s[cc];
                    float v1 = acc[t][j][1] + b1s[cc + 1];
                    float v2 = acc[t][j][2] + b1s[cc];
                    float v3 = acc[t][j][3] + b1s[cc + 1];
                    v0 = 0.5f * v0 * (1.0f + erff(v0 * 0.70710678f));
                    v1 = 0.5f * v1 * (1.0f + erff(v1 * 0.70710678f));
                    v2 = 0.5f * v2 * (1.0f + erff(v2 * 0.70710678f));
                    v3 = 0.5f * v3 * (1.0f + erff(v3 * 0.70710678f));
                    storeA(smc, r,     cc, v0, v1);
                    storeA(smc, r + 8, cc, v2, v3);
                    acc[t][j][0] = 0.0f; acc[t][j][1] = 0.0f;
                    acc[t][j][2] = 0.0f; acc[t][j][3] = 0.0f;
                }
            __syncthreads();   // H visible to partner warps
        }

        // ---- MMA over this 32-K chunk (2 k-steps of 16) ----
        #pragma unroll
        for (int ks = 0; ks < 2; ks++) {
            const uint32_t k0 = (uint32_t)(kc * 32 + ks * 16) + a_koff;
            uint32_t ahi[2][4], alo[2][4];
            #pragma unroll
            for (int t = 0; t < 2; t++) {
                uint32_t ra = (a_row + (uint32_t)(t * 16)) * A_STRIDE + k0;
                ldm_x4(ahi[t], sb + AHI_OFF + ra * 2);
                ldm_x4(alo[t], sb + ALO_OFF + ra * 2);
            }
            const uint32_t bk = b_base + (uint32_t)(buf * 40960 + ks * 32);
            #pragma unroll
            for (int j = 0; j < 16; j++) {
                uint32_t bhi[2], blo[2];
                ldm_x2(bhi, bk + (uint32_t)(j * 640));
                ldm_x2(blo, bk + (uint32_t)(j * 640) + 20480u);
                #pragma unroll
                for (int t = 0; t < 2; t++) {
                    mma16816(acc[t][j], ahi[t], bhi);
                    mma16816(acc[t][j], alo[t], bhi);
                    mma16816(acc[t][j], ahi[t], blo);
                }
            }
        }

        if (c + 2 < 16) {
            __syncthreads();   // everyone done reading stage[buf]
            const __half* nxt = (c + 2 < 8) ? (g_w1c + (size_t)(c + 2) * CHUNK_HALFS)
                                            : (g_w2c + (size_t)(c - 6) * CHUNK_HALFS);
            fill_stage(sb + BST_OFF + buf * 40960, nxt, tid);
            CP_COMMIT();
        }
    }

    // ---- epilogue 2: bias + mean over supernode (warp-local: 32 rows) ----
    #pragma unroll
    for (int j = 0; j < 16; j++) {
        float s0 = 0.0f, s1 = 0.0f;
        #pragma unroll
        for (int t = 0; t < 2; t++) {
            s0 += acc[t][j][0] + acc[t][j][2];
            s1 += acc[t][j][1] + acc[t][j][3];
        }
        #pragma unroll
        for (int off = 4; off < 32; off <<= 1) {
            s0 += __shfl_xor_sync(0xFFFFFFFFu, s0, off);
            s1 += __shfl_xor_sync(0xFFFFFFFFu, s1, off);
        }
        if (lane < 4) {
            int cc = ng * 128 + j * 8 + lane * 2;
            int s  = blockIdx.x * 4 + mg;
            float2 v;
            v.x = s0 * (1.0f / 32.0f) + b2s[cc];
            v.y = s1 * (1.0f / 32.0f) + b2s[cc + 1];
            *(float2*)&g_agg[(size_t)s * HIDDEN + cc] = v;
        }
    }
}

// ---------------------------------------------------------------------------
// Kernel 2 (unchanged from passing round 1): out = [agg | sincos(sup_pos)] @ wp + bp
// ---------------------------------------------------------------------------
#define BLK_S     64
#define AT_STRIDE 68
#define KCHUNK    32

__global__ __launch_bounds__(256, 1)
void out_proj_kernel(const float* __restrict__ pos,
                     const int* __restrict__ sup_idx,
                     const float* __restrict__ wp, const float* __restrict__ bp,
                     float* __restrict__ out) {
    extern __shared__ float smf[];
    float* At   = smf;
    float* Wb   = At + 512 * AT_STRIDE;
    float* spos = Wb + KCHUNK * 256;

    const int tid = threadIdx.x;
    const int s0  = blockIdx.x * BLK_S;

    #pragma unroll 4
    for (int r = 0; r < BLK_S; r++)
        At[tid * AT_STRIDE + r] = g_agg[(s0 + r) * HIDDEN + tid];

    if (tid < BLK_S) {
        int si = sup_idx[s0 + tid];
        spos[tid * 3 + 0] = pos[si * 3 + 0];
        spos[tid * 3 + 1] = pos[si * 3 + 1];
        spos[tid * 3 + 2] = pos[si * 3 + 2];
    }
    {
        int k = 508 + (tid >> 6);
        int r = tid & 63;
        At[k * AT_STRIDE + r] = 0.0f;
    }
    __syncthreads();

    for (int idx = tid; idx < BLK_S * 252; idx += 256) {
        int r  = idx / 252;
        int kk = idx - r * 252;
        int d  = kk / 84;
        int j  = kk - d * 84;
        int jj = (j < 42) ? j : (j - 42);
        float om = expf(-(float)jj * OM3_C);
        float v  = spos[r * 3 + d] * om;
        At[(256 + kk) * AT_STRIDE + r] = (j < 42) ? sinf(v) : cosf(v);
    }

    const int tx = tid & 31;
    const int ty = tid >> 5;
    const int r0 = ty * 8;

    float biasv[8];
    #pragma unroll
    for (int g = 0; g < 2; g++)
        #pragma unroll
        for (int u = 0; u < 4; u++) biasv[g * 4 + u] = bp[tx * 4 + g * 128 + u];

    float acc[8][8];
    #pragma unroll
    for (int i = 0; i < 8; i++)
        #pragma unroll
        for (int j = 0; j < 8; j++) acc[i][j] = 0.0f;

    for (int kt = 0; kt < 512 / KCHUNK; kt++) {
        __syncthreads();
        {
            const float4* src = (const float4*)(wp + kt * KCHUNK * 256);
            float4* dst = (float4*)Wb;
            #pragma unroll
            for (int i = 0; i < 8; i++) dst[i * 256 + tid] = src[i * 256 + tid];
        }
        __syncthreads();
        #pragma unroll 8
        for (int kk = 0; kk < KCHUNK; kk++) {
            int k = kt * KCHUNK + kk;
            float4 a0 = *(const float4*)&At[k * AT_STRIDE + r0];
            float4 a1 = *(const float4*)&At[k * AT_STRIDE + r0 + 4];
            float a[8] = {a0.x, a0.y, a0.z, a0.w, a1.x, a1.y, a1.z, a1.w};
            float b[8];
            #pragma unroll
            for (int g = 0; g < 2; g++) {
                float4 bb = *(const float4*)&Wb[kk * 256 + tx * 4 + g * 128];
                b[g * 4 + 0] = bb.x; b[g * 4 + 1] = bb.y;
                b[g * 4 + 2] = bb.z; b[g * 4 + 3] = bb.w;
            }
            #pragma unroll
            for (int i = 0; i < 8; i++)
                #pragma unroll
                for (int j = 0; j < 8; j++) acc[i][j] += a[i] * b[j];
        }
    }

    #pragma unroll
    for (int i = 0; i < 8; i++)
        #pragma unroll
        for (int g = 0; g < 2; g++) {
            float4 v;
            v.x = acc[i][g * 4 + 0] + biasv[g * 4 + 0];
            v.y = acc[i][g * 4 + 1] + biasv[g * 4 + 1];
            v.z = acc[i][g * 4 + 2] + biasv[g * 4 + 2];
            v.w = acc[i][g * 4 + 3] + biasv[g * 4 + 3];
            *(float4*)&out[(size_t)(s0 + r0 + i) * HIDDEN + tx * 4 + g * 128] = v;
        }
}

// ---------------------------------------------------------------------------
extern "C" void kernel_launch(void* const* d_in, const int* in_sizes, int n_in,
                              void* d_out, int out_size) {
    const float* pos     = (const float*)d_in[0];
    const int*   sup_idx = (const int*)d_in[1];
    const int*   src_idx = (const int*)d_in[2];
    const float* w1 = (const float*)d_in[4];
    const float* b1 = (const float*)d_in[5];
    const float* w2 = (const float*)d_in[6];
    const float* b2 = (const float*)d_in[7];
    const float* wp = (const float*)d_in[8];
    const float* bp = (const float*)d_in[9];
    float* out = (float*)d_out;

    cudaFuncSetAttribute(edge_mlp_mma,
                         cudaFuncAttributeMaxDynamicSharedMemorySize, SMEM_EDGE);
    const int smem2 = (512 * AT_STRIDE + KCHUNK * 256 + BLK_S * 3) * 4;
    cudaFuncSetAttribute(out_proj_kernel,
                         cudaFuncAttributeMaxDynamicSharedMemorySize, smem2);

    prep_weights<<<512, 256>>>(w1, w2);
    edge_mlp_mma<<<NUM_EDGES / 128, 256, SMEM_EDGE>>>(pos, sup_idx, src_idx, b1, b2);
    out_proj_kernel<<<NUM_SUP / BLK_S, 256, smem2>>>(pos, sup_idx, wp, bp, out);
}

// round 4
// speedup vs baseline: 3.0534x; 1.2608x over previous
#include <cuda_runtime.h>
#include <cuda_fp16.h>
#include <math.h>
#include <stdint.h>

#define NUM_POINTS 500000
#define NUM_SUP    8192
#define DEGREE     32
#define NUM_EDGES  (NUM_SUP * DEGREE)   // 262144
#define HIDDEN     256

#define OM4_C 0.2878231366242559f   // ln(10000)/32
#define OM3_C 0.2192938183803854f   // ln(10000)/42

// ---------------- global scratch ----------------
__device__ float g_agg[NUM_SUP * HIDDEN];
// weight chunks: [8 kchunks][2 terms(hi,lo)][256 n][40 k-padded] half
#define CHUNK_HALFS (2 * 256 * 40)            // 20480 half = 40960 B
__device__ __align__(256) __half g_w1c[8 * CHUNK_HALFS];
__device__ __align__(256) __half g_w2c[8 * CHUNK_HALFS];

// ---------------- edge-kernel smem layout (bytes) ----------------
#define A_STRIDE  264                          // halfs per row (256 + 8 pad)
#define A_OFF     0                            // 128 x 264 half = 67584 B
#define BST_OFF   67584                        // 3 stages x 40960 B = 122880
#define REL_OFF   190464                       // 128 x 4 float
#define B1S_OFF   192512                       // 256 float
#define B2S_OFF   193536                       // 256 float
#define SMEM_EDGE 194560

// ---------------- PTX helpers ----------------
__device__ __forceinline__ uint32_t smem_u32(const void* p) {
    uint32_t a;
    asm("{ .reg .u64 t; cvta.to.shared.u64 t, %1; cvt.u32.u64 %0, t; }" : "=r"(a) : "l"(p));
    return a;
}
__device__ __forceinline__ void ldm_x4(uint32_t* r, uint32_t addr) {
    asm volatile("ldmatrix.sync.aligned.m8n8.x4.shared.b16 {%0,%1,%2,%3}, [%4];"
                 : "=r"(r[0]), "=r"(r[1]), "=r"(r[2]), "=r"(r[3]) : "r"(addr));
}
__device__ __forceinline__ void mma16816(float* d, const uint32_t* a, const uint32_t* b) {
    asm volatile("mma.sync.aligned.m16n8k16.row.col.f32.f16.f16.f32 "
                 "{%0,%1,%2,%3}, {%4,%5,%6,%7}, {%8,%9}, {%0,%1,%2,%3};"
                 : "+f"(d[0]), "+f"(d[1]), "+f"(d[2]), "+f"(d[3])
                 : "r"(a[0]), "r"(a[1]), "r"(a[2]), "r"(a[3]), "r"(b[0]), "r"(b[1]));
}
__device__ __forceinline__ void cp16(uint32_t dst, const void* src) {
    asm volatile("cp.async.cg.shared.global [%0], [%1], 16;" :: "r"(dst), "l"(src) : "memory");
}
#define CP_COMMIT() asm volatile("cp.async.commit_group;" ::: "memory")
#define CP_WAIT2()  asm volatile("cp.async.wait_group 2;" ::: "memory")
#define CP_WAIT1()  asm volatile("cp.async.wait_group 1;" ::: "memory")
#define CP_WAIT0()  asm volatile("cp.async.wait_group 0;" ::: "memory")

// store fp16 pair at A[m][c], A[m][c+1]  (c even)
__device__ __forceinline__ void storeA(char* smc, int m, int c, float x, float y) {
    *(__half2*)(smc + A_OFF + (uint32_t)(m * A_STRIDE + c) * 2) = __floats2half2_rn(x, y);
}

// fill one 40960 B weight stage (256 threads x 10 x 16 B)
__device__ __forceinline__ void fill_stage(uint32_t dst_sb, const __half* src, int tid) {
    const char* g = (const char*)src + tid * 16;
    uint32_t d = dst_sb + tid * 16;
    #pragma unroll
    for (int i = 0; i < 10; i++) cp16(d + i * 4096, g + i * 4096);
}
__device__ __forceinline__ const __half* chunk_src(int c) {
    return (c < 8) ? (g_w1c + (size_t)c * CHUNK_HALFS)
                   : (g_w2c + (size_t)(c - 8) * CHUNK_HALFS);
}

// ---------------------------------------------------------------------------
// prep: split w[k][n] (fp32 row-major) into hi/lo fp16, transposed to n-major,
// padded chunk layout [kc][term][n][40] — runtime streaming is a raw memcpy.
// ---------------------------------------------------------------------------
__global__ void prep_weights(const float* __restrict__ w1, const float* __restrict__ w2) {
    int idx = blockIdx.x * blockDim.x + threadIdx.x;   // 131072
    const float* w = (idx < 65536) ? w1 : w2;
    __half* dst = (idx < 65536) ? g_w1c : g_w2c;
    int i = idx & 65535;
    int k = i >> 8, n = i & 255;
    float v = w[i];
    __half hi = __float2half_rn(v);
    float lo = v - __half2float(hi);
    int kc = k >> 5, kk = k & 31;
    dst[(size_t)kc * CHUNK_HALFS + (0 * 256 + n) * 40 + kk] = hi;
    dst[(size_t)kc * CHUNK_HALFS + (1 * 256 + n) * 40 + kk] = __float2half_rn(lo);
}

// ---------------------------------------------------------------------------
// Edge kernel: 128 edges/CTA, 2-term HMMA (A fp16, B hi/lo), fused epilogues.
// ---------------------------------------------------------------------------
__global__ __launch_bounds__(256, 1)
void edge_mlp_mma(const float* __restrict__ pos,
                  const int* __restrict__ sup_idx,
                  const int* __restrict__ src_idx,
                  const float* __restrict__ b1,
                  const float* __restrict__ b2) {
    extern __shared__ char smc[];
    const uint32_t sb = smem_u32(smc);
    const int tid  = threadIdx.x;
    const int wid  = tid >> 5;
    const int lane = tid & 31;
    const int mg   = wid & 3;     // M-group: rows [mg*32, mg*32+32) = supernode mg
    const int ng   = wid >> 2;    // N-group: cols [ng*128, ng*128+128)

    float* b1s = (float*)(smc + B1S_OFF);
    float* b2s = (float*)(smc + B2S_OFF);
    b1s[tid] = b1[tid];
    b2s[tid] = b2[tid];

    // prefetch first three weight chunks (3-stage pipeline)
    fill_stage(sb + BST_OFF,             chunk_src(0), tid); CP_COMMIT();
    fill_stage(sb + BST_OFF + 40960,     chunk_src(1), tid); CP_COMMIT();
    fill_stage(sb + BST_OFF + 2 * 40960, chunk_src(2), tid); CP_COMMIT();

    // ---- relative positions ----
    if (tid < 128) {
        int e = blockIdx.x * 128 + tid;
        int si = sup_idx[e >> 5], sr = src_idx[e];
        float dx = pos[si * 3 + 0] - pos[sr * 3 + 0];
        float dy = pos[si * 3 + 1] - pos[sr * 3 + 1];
        float dz = pos[si * 3 + 2] - pos[sr * 3 + 2];
        float* rb = (float*)(smc + REL_OFF);
        rb[tid * 4 + 0] = dx; rb[tid * 4 + 1] = dy; rb[tid * 4 + 2] = dz;
        rb[tid * 4 + 3] = sqrtf(dx * dx + dy * dy + dz * dz);
    }
    __syncthreads();

    // ---- sincos embed -> A fp16 (thread: row m=tid&127, half h=tid>>7) ----
    {
        const float* rb = (const float*)(smc + REL_OFF);
        int m = tid & 127, h = tid >> 7;
        float r2 = rb[m * 4 + h * 2], r3 = rb[m * 4 + h * 2 + 1];
        #pragma unroll 4
        for (int j = 0; j < 64; j += 2) {
            int jj = j & 31;
            float om0 = __expf(-(float)jj * OM4_C);
            float om1 = __expf(-(float)(jj + 1) * OM4_C);
            float a0 = r2 * om0, a1 = r2 * om1;
            float c0 = r3 * om0, c1 = r3 * om1;
            if (j < 32) {
                storeA(smc, m, (h * 2) * 64 + j,     __sinf(a0), __sinf(a1));
                storeA(smc, m, (h * 2 + 1) * 64 + j, __sinf(c0), __sinf(c1));
            } else {
                storeA(smc, m, (h * 2) * 64 + j,     __cosf(a0), __cosf(a1));
                storeA(smc, m, (h * 2 + 1) * 64 + j, __cosf(c0), __cosf(c1));
            }
        }
    }
    __syncthreads();   // A ready for all warps

    float acc[2][16][4];
    #pragma unroll
    for (int t = 0; t < 2; t++)
        #pragma unroll
        for (int j = 0; j < 16; j++)
            #pragma unroll
            for (int q = 0; q < 4; q++) acc[t][j][q] = 0.0f;

    // A ldmatrix lane bases (x4: 16 rows x 2 k-halves)
    const uint32_t a_row  = (uint32_t)(mg * 32 + (lane & 15));
    const uint32_t a_koff = (uint32_t)((lane >> 4) * 8);
    // B ldmatrix lane bases (x4 over an n-tile pair: 16 n-rows x 2 k-halves)
    const int bn  = (lane & 7) | (((lane >> 4) & 1) << 3);   // 0..15
    const int bkh = (lane >> 3) & 1;
    const uint32_t b_base = sb + BST_OFF +
        (uint32_t)(((ng * 128 + bn) * 40 + bkh * 8) * 2);

    const int l4 = lane >> 2;
    const int l2 = (lane & 3) * 2;

    #pragma unroll 1
    for (int c = 0; c < 16; c++) {
        const int buf = c % 3;
        const int kc  = c & 7;
        if (c <= 13) { CP_WAIT2(); } else if (c == 14) { CP_WAIT1(); } else { CP_WAIT0(); }
        __syncthreads();   // stage[buf] visible to all

        if (c == 8) {
            // ---- epilogue 1: bias + exact GELU -> rewrite A (fp16) ----
            #pragma unroll
            for (int t = 0; t < 2; t++)
                #pragma unroll
                for (int j = 0; j < 16; j++) {
                    int r  = mg * 32 + t * 16 + l4;
                    int cc = ng * 128 + j * 8 + l2;
                    float v0 = acc[t][j][0] + b1s[cc];
                    float v1 = acc[t][j][1] + b1s[cc + 1];
                    float v2 = acc[t][j][2] + b1s[cc];
                    float v3 = acc[t][j][3] + b1s[cc + 1];
                    v0 = 0.5f * v0 * (1.0f + erff(v0 * 0.70710678f));
                    v1 = 0.5f * v1 * (1.0f + erff(v1 * 0.70710678f));
                    v2 = 0.5f * v2 * (1.0f + erff(v2 * 0.70710678f));
                    v3 = 0.5f * v3 * (1.0f + erff(v3 * 0.70710678f));
                    storeA(smc, r,     cc, v0, v1);
                    storeA(smc, r + 8, cc, v2, v3);
                    acc[t][j][0] = 0.0f; acc[t][j][1] = 0.0f;
                    acc[t][j][2] = 0.0f; acc[t][j][3] = 0.0f;
                }
            __syncthreads();   // H visible to partner warps
        }

        // ---- MMA over this 32-K chunk (2 k-steps of 16) ----
        #pragma unroll
        for (int ks = 0; ks < 2; ks++) {
            const uint32_t k0 = (uint32_t)(kc * 32 + ks * 16) + a_koff;
            uint32_t ah[2][4];
            #pragma unroll
            for (int t = 0; t < 2; t++) {
                uint32_t ra = (a_row + (uint32_t)(t * 16)) * A_STRIDE + k0;
                ldm_x4(ah[t], sb + A_OFF + ra * 2);
            }
            const uint32_t bk = b_base + (uint32_t)(buf * 40960 + ks * 32);
            #pragma unroll
            for (int jp = 0; jp < 8; jp++) {
                uint32_t bh[4], bl[4];
                uint32_t ba = bk + (uint32_t)(jp * 1280);   // 16 n-rows * 80 B
                ldm_x4(bh, ba);
                ldm_x4(bl, ba + 20480u);
                #pragma unroll
                for (int t = 0; t < 2; t++)
                    #pragma unroll
                    for (int jj = 0; jj < 2; jj++) {
                        mma16816(acc[t][jp * 2 + jj], ah[t], bh + jj * 2);
                        mma16816(acc[t][jp * 2 + jj], ah[t], bl + jj * 2);
                    }
            }
        }

        if (c + 3 < 16) {
            __syncthreads();   // everyone done reading stage[buf]
            fill_stage(sb + BST_OFF + buf * 40960, chunk_src(c + 3), tid);
            CP_COMMIT();
        }
    }

    // ---- epilogue 2: bias + mean over supernode (warp-local: 32 rows) ----
    #pragma unroll
    for (int j = 0; j < 16; j++) {
        float s0 = 0.0f, s1 = 0.0f;
        #pragma unroll
        for (int t = 0; t < 2; t++) {
            s0 += acc[t][j][0] + acc[t][j][2];
            s1 += acc[t][j][1] + acc[t][j][3];
        }
        #pragma unroll
        for (int off = 4; off < 32; off <<= 1) {
            s0 += __shfl_xor_sync(0xFFFFFFFFu, s0, off);
            s1 += __shfl_xor_sync(0xFFFFFFFFu, s1, off);
        }
        if (lane < 4) {
            int cc = ng * 128 + j * 8 + lane * 2;
            int s  = blockIdx.x * 4 + mg;
            float2 v;
            v.x = s0 * (1.0f / 32.0f) + b2s[cc];
            v.y = s1 * (1.0f / 32.0f) + b2s[cc + 1];
            *(float2*)&g_agg[(size_t)s * HIDDEN + cc] = v;
        }
    }
}

// ---------------------------------------------------------------------------
// Kernel 2: out = [agg | sincos(sup_pos)] @ wp + bp
// ---------------------------------------------------------------------------
#define BLK_S     64
#define AT_STRIDE 68
#define KCHUNK    32

__global__ __launch_bounds__(256, 1)
void out_proj_kernel(const float* __restrict__ pos,
                     const int* __restrict__ sup_idx,
                     const float* __restrict__ wp, const float* __restrict__ bp,
                     float* __restrict__ out) {
    extern __shared__ float smf[];
    float* At   = smf;
    float* Wb   = At + 512 * AT_STRIDE;
    float* spos = Wb + KCHUNK * 256;

    const int tid = threadIdx.x;
    const int s0  = blockIdx.x * BLK_S;

    #pragma unroll 4
    for (int r = 0; r < BLK_S; r++)
        At[tid * AT_STRIDE + r] = g_agg[(s0 + r) * HIDDEN + tid];

    if (tid < BLK_S) {
        int si = sup_idx[s0 + tid];
        spos[tid * 3 + 0] = pos[si * 3 + 0];
        spos[tid * 3 + 1] = pos[si * 3 + 1];
        spos[tid * 3 + 2] = pos[si * 3 + 2];
    }
    {
        int k = 508 + (tid >> 6);
        int r = tid & 63;
        At[k * AT_STRIDE + r] = 0.0f;
    }
    __syncthreads();

    for (int idx = tid; idx < BLK_S * 252; idx += 256) {
        int r  = idx / 252;
        int kk = idx - r * 252;
        int d  = kk / 84;
        int j  = kk - d * 84;
        int jj = (j < 42) ? j : (j - 42);
        float om = expf(-(float)jj * OM3_C);
        float v  = spos[r * 3 + d] * om;
        At[(256 + kk) * AT_STRIDE + r] = (j < 42) ? sinf(v) : cosf(v);
    }

    const int tx = tid & 31;
    const int ty = tid >> 5;
    const int r0 = ty * 8;

    float biasv[8];
    #pragma unroll
    for (int g = 0; g < 2; g++)
        #pragma unroll
        for (int u = 0; u < 4; u++) biasv[g * 4 + u] = bp[tx * 4 + g * 128 + u];

    float acc[8][8];
    #pragma unroll
    for (int i = 0; i < 8; i++)
        #pragma unroll
        for (int j = 0; j < 8; j++) acc[i][j] = 0.0f;

    for (int kt = 0; kt < 512 / KCHUNK; kt++) {
        __syncthreads();
        {
            const float4* src = (const float4*)(wp + kt * KCHUNK * 256);
            float4* dst = (float4*)Wb;
            #pragma unroll
            for (int i = 0; i < 8; i++) dst[i * 256 + tid] = src[i * 256 + tid];
        }
        __syncthreads();
        #pragma unroll 8
        for (int kk = 0; kk < KCHUNK; kk++) {
            int k = kt * KCHUNK + kk;
            float4 a0 = *(const float4*)&At[k * AT_STRIDE + r0];
            float4 a1 = *(const float4*)&At[k * AT_STRIDE + r0 + 4];
            float a[8] = {a0.x, a0.y, a0.z, a0.w, a1.x, a1.y, a1.z, a1.w};
            float b[8];
            #pragma unroll
            for (int g = 0; g < 2; g++) {
                float4 bb = *(const float4*)&Wb[kk * 256 + tx * 4 + g * 128];
                b[g * 4 + 0] = bb.x; b[g * 4 + 1] = bb.y;
                b[g * 4 + 2] = bb.z; b[g * 4 + 3] = bb.w;
            }
            #pragma unroll
            for (int i = 0; i < 8; i++)
                #pragma unroll
                for (int j = 0; j < 8; j++) acc[i][j] += a[i] * b[j];
        }
    }

    #pragma unroll
    for (int i = 0; i < 8; i++)
        #pragma unroll
        for (int g = 0; g < 2; g++) {
            float4 v;
            v.x = acc[i][g * 4 + 0] + biasv[g * 4 + 0];
            v.y = acc[i][g * 4 + 1] + biasv[g * 4 + 1];
            v.z = acc[i][g * 4 + 2] + biasv[g * 4 + 2];
            v.w = acc[i][g * 4 + 3] + biasv[g * 4 + 3];
            *(float4*)&out[(size_t)(s0 + r0 + i) * HIDDEN + tx * 4 + g * 128] = v;
        }
}

// ---------------------------------------------------------------------------
extern "C" void kernel_launch(void* const* d_in, const int* in_sizes, int n_in,
                              void* d_out, int out_size) {
    const float* pos     = (const float*)d_in[0];
    const int*   sup_idx = (const int*)d_in[1];
    const int*   src_idx = (const int*)d_in[2];
    const float* w1 = (const float*)d_in[4];
    const float* b1 = (const float*)d_in[5];
    const float* w2 = (const float*)d_in[6];
    const float* b2 = (const float*)d_in[7];
    const float* wp = (const float*)d_in[8];
    const float* bp = (const float*)d_in[9];
    float* out = (float*)d_out;

    cudaFuncSetAttribute(edge_mlp_mma,
                         cudaFuncAttributeMaxDynamicSharedMemorySize, SMEM_EDGE);
    const int smem2 = (512 * AT_STRIDE + KCHUNK * 256 + BLK_S * 3) * 4;
    cudaFuncSetAttribute(out_proj_kernel,
                         cudaFuncAttributeMaxDynamicSharedMemorySize, smem2);

    prep_weights<<<512, 256>>>(w1, w2);
    edge_mlp_mma<<<NUM_EDGES / 128, 256, SMEM_EDGE>>>(pos, sup_idx, src_idx, b1, b2);
    out_proj_kernel<<<NUM_SUP / BLK_S, 256, smem2>>>(pos, sup_idx, wp, bp, out);
}

// round 5
// speedup vs baseline: 4.1023x; 1.3435x over previous
#include <cuda_runtime.h>
#include <cuda_fp16.h>
#include <math.h>
#include <stdint.h>

#define NUM_POINTS 500000
#define NUM_SUP    8192
#define DEGREE     32
#define NUM_EDGES  (NUM_SUP * DEGREE)   // 262144
#define HIDDEN     256

#define OM4_C 0.2878231366242559f   // ln(10000)/32
#define OM3_C 0.2192938183803854f   // ln(10000)/42

// ---------------- global scratch ----------------
__device__ float g_agg[NUM_SUP * HIDDEN];
// weight chunks: [8 kchunks][256 n][40 k-padded] half  (single fp16 term)
#define CHUNK_HALFS (256 * 40)                // 10240 half = 20480 B
#define CHUNK_BYTES 20480
__device__ __align__(256) __half g_w1c[8 * CHUNK_HALFS];
__device__ __align__(256) __half g_w2c[8 * CHUNK_HALFS];

// ---------------- edge-kernel smem layout (bytes) ----------------
#define A_STRIDE  264                          // halfs per row (256 + 8 pad)
#define A_OFF     0                            // 128 x 264 half = 67584 B
#define BST_OFF   67584                        // 4 stages x 20480 B = 81920
#define REL_OFF   149504                       // 128 x 4 float
#define B1S_OFF   151552                       // 256 float
#define B2S_OFF   152576                       // 256 float
#define SMEM_EDGE 153600

// ---------------- PTX helpers ----------------
__device__ __forceinline__ uint32_t smem_u32(const void* p) {
    uint32_t a;
    asm("{ .reg .u64 t; cvta.to.shared.u64 t, %1; cvt.u32.u64 %0, t; }" : "=r"(a) : "l"(p));
    return a;
}
__device__ __forceinline__ void ldm_x4(uint32_t* r, uint32_t addr) {
    asm volatile("ldmatrix.sync.aligned.m8n8.x4.shared.b16 {%0,%1,%2,%3}, [%4];"
                 : "=r"(r[0]), "=r"(r[1]), "=r"(r[2]), "=r"(r[3]) : "r"(addr));
}
__device__ __forceinline__ void mma16816(float* d, const uint32_t* a, const uint32_t* b) {
    asm volatile("mma.sync.aligned.m16n8k16.row.col.f32.f16.f16.f32 "
                 "{%0,%1,%2,%3}, {%4,%5,%6,%7}, {%8,%9}, {%0,%1,%2,%3};"
                 : "+f"(d[0]), "+f"(d[1]), "+f"(d[2]), "+f"(d[3])
                 : "r"(a[0]), "r"(a[1]), "r"(a[2]), "r"(a[3]), "r"(b[0]), "r"(b[1]));
}
__device__ __forceinline__ void cp16(uint32_t dst, const void* src) {
    asm volatile("cp.async.cg.shared.global [%0], [%1], 16;" :: "r"(dst), "l"(src) : "memory");
}
#define CP_COMMIT() asm volatile("cp.async.commit_group;" ::: "memory")
#define CP_WAIT2()  asm volatile("cp.async.wait_group 2;" ::: "memory")
#define CP_WAIT1()  asm volatile("cp.async.wait_group 1;" ::: "memory")
#define CP_WAIT0()  asm volatile("cp.async.wait_group 0;" ::: "memory")

// store fp16 pair at A[m][c], A[m][c+1]  (c even)
__device__ __forceinline__ void storeA(char* smc, int m, int c, float x, float y) {
    *(__half2*)(smc + A_OFF + (uint32_t)(m * A_STRIDE + c) * 2) = __floats2half2_rn(x, y);
}

// fill one 20480 B weight stage (256 threads x 5 x 16 B)
__device__ __forceinline__ void fill_stage(uint32_t dst_sb, const __half* src, int tid) {
    const char* g = (const char*)src + tid * 16;
    uint32_t d = dst_sb + tid * 16;
    #pragma unroll
    for (int i = 0; i < 5; i++) cp16(d + i * 4096, g + i * 4096);
}
__device__ __forceinline__ const __half* chunk_src(int c) {
    return (c < 8) ? (g_w1c + (size_t)c * CHUNK_HALFS)
                   : (g_w2c + (size_t)(c - 8) * CHUNK_HALFS);
}

// ---------------------------------------------------------------------------
// prep: fp16-round w[k][n] (fp32 row-major), transposed to n-major,
// padded chunk layout [kc][n][40] — runtime streaming is a raw memcpy.
// ---------------------------------------------------------------------------
__global__ void prep_weights(const float* __restrict__ w1, const float* __restrict__ w2) {
    int idx = blockIdx.x * blockDim.x + threadIdx.x;   // 131072
    const float* w = (idx < 65536) ? w1 : w2;
    __half* dst = (idx < 65536) ? g_w1c : g_w2c;
    int i = idx & 65535;
    int k = i >> 8, n = i & 255;
    int kc = k >> 5, kk = k & 31;
    dst[(size_t)kc * CHUNK_HALFS + n * 40 + kk] = __float2half_rn(w[i]);
}

// ---------------------------------------------------------------------------
// Edge kernel: 128 edges/CTA, single-term fp16 HMMA, fused GELU + segment mean.
// ---------------------------------------------------------------------------
__global__ __launch_bounds__(256, 1)
void edge_mlp_mma(const float* __restrict__ pos,
                  const int* __restrict__ sup_idx,
                  const int* __restrict__ src_idx,
                  const float* __restrict__ b1,
                  const float* __restrict__ b2) {
    extern __shared__ char smc[];
    const uint32_t sb = smem_u32(smc);
    const int tid  = threadIdx.x;
    const int wid  = tid >> 5;
    const int lane = tid & 31;
    const int mg   = wid & 3;     // M-group: rows [mg*32, mg*32+32) = supernode mg
    const int ng   = wid >> 2;    // N-group: cols [ng*128, ng*128+128)

    float* b1s = (float*)(smc + B1S_OFF);
    float* b2s = (float*)(smc + B2S_OFF);
    b1s[tid] = b1[tid];
    b2s[tid] = b2[tid];

    // prefetch first three weight chunks (4-stage pipeline, 3 in flight)
    fill_stage(sb + BST_OFF,                   chunk_src(0), tid); CP_COMMIT();
    fill_stage(sb + BST_OFF + CHUNK_BYTES,     chunk_src(1), tid); CP_COMMIT();
    fill_stage(sb + BST_OFF + 2 * CHUNK_BYTES, chunk_src(2), tid); CP_COMMIT();

    // ---- relative positions ----
    if (tid < 128) {
        int e = blockIdx.x * 128 + tid;
        int si = sup_idx[e >> 5], sr = src_idx[e];
        float dx = pos[si * 3 + 0] - pos[sr * 3 + 0];
        float dy = pos[si * 3 + 1] - pos[sr * 3 + 1];
        float dz = pos[si * 3 + 2] - pos[sr * 3 + 2];
        float* rb = (float*)(smc + REL_OFF);
        rb[tid * 4 + 0] = dx; rb[tid * 4 + 1] = dy; rb[tid * 4 + 2] = dz;
        rb[tid * 4 + 3] = sqrtf(dx * dx + dy * dy + dz * dz);
    }
    __syncthreads();

    // ---- sincos embed -> A fp16 (thread: row m=tid&127, half h=tid>>7) ----
    {
        const float* rb = (const float*)(smc + REL_OFF);
        int m = tid & 127, h = tid >> 7;
        float r2 = rb[m * 4 + h * 2], r3 = rb[m * 4 + h * 2 + 1];
        #pragma unroll 4
        for (int j = 0; j < 64; j += 2) {
            int jj = j & 31;
            float om0 = __expf(-(float)jj * OM4_C);
            float om1 = __expf(-(float)(jj + 1) * OM4_C);
            float a0 = r2 * om0, a1 = r2 * om1;
            float c0 = r3 * om0, c1 = r3 * om1;
            if (j < 32) {
                storeA(smc, m, (h * 2) * 64 + j,     __sinf(a0), __sinf(a1));
                storeA(smc, m, (h * 2 + 1) * 64 + j, __sinf(c0), __sinf(c1));
            } else {
                storeA(smc, m, (h * 2) * 64 + j,     __cosf(a0), __cosf(a1));
                storeA(smc, m, (h * 2 + 1) * 64 + j, __cosf(c0), __cosf(c1));
            }
        }
    }
    __syncthreads();   // A ready for all warps

    float acc[2][16][4];
    #pragma unroll
    for (int t = 0; t < 2; t++)
        #pragma unroll
        for (int j = 0; j < 16; j++)
            #pragma unroll
            for (int q = 0; q < 4; q++) acc[t][j][q] = 0.0f;

    // A ldmatrix lane bases (x4: 16 rows x 2 k-halves)
    const uint32_t a_row  = (uint32_t)(mg * 32 + (lane & 15));
    const uint32_t a_koff = (uint32_t)((lane >> 4) * 8);
    // B ldmatrix lane bases (x4 over an n-tile pair: 16 n-rows x 2 k-halves)
    const int bn  = (lane & 7) | (((lane >> 4) & 1) << 3);   // 0..15
    const int bkh = (lane >> 3) & 1;
    const uint32_t b_base = sb + BST_OFF +
        (uint32_t)(((ng * 128 + bn) * 40 + bkh * 8) * 2);

    const int l4 = lane >> 2;
    const int l2 = (lane & 3) * 2;

    #pragma unroll 1
    for (int c = 0; c < 16; c++) {
        const int buf = c & 3;
        const int kc  = c & 7;
        if (c <= 13) { CP_WAIT2(); } else if (c == 14) { CP_WAIT1(); } else { CP_WAIT0(); }
        __syncthreads();   // stage[buf] visible; stage[(c+3)&3] free (chunk c-1 consumed)

        // issue next fill immediately (destination buffer freed at the sync above)
        if (c + 3 < 16) {
            fill_stage(sb + BST_OFF + ((c + 3) & 3) * CHUNK_BYTES, chunk_src(c + 3), tid);
            CP_COMMIT();
        }

        if (c == 8) {
            // ---- epilogue 1: bias + exact GELU -> rewrite A (fp16) ----
            #pragma unroll
            for (int t = 0; t < 2; t++)
                #pragma unroll
                for (int j = 0; j < 16; j++) {
                    int r  = mg * 32 + t * 16 + l4;
                    int cc = ng * 128 + j * 8 + l2;
                    float v0 = acc[t][j][0] + b1s[cc];
                    float v1 = acc[t][j][1] + b1s[cc + 1];
                    float v2 = acc[t][j][2] + b1s[cc];
                    float v3 = acc[t][j][3] + b1s[cc + 1];
                    v0 = 0.5f * v0 * (1.0f + erff(v0 * 0.70710678f));
                    v1 = 0.5f * v1 * (1.0f + erff(v1 * 0.70710678f));
                    v2 = 0.5f * v2 * (1.0f + erff(v2 * 0.70710678f));
                    v3 = 0.5f * v3 * (1.0f + erff(v3 * 0.70710678f));
                    storeA(smc, r,     cc, v0, v1);
                    storeA(smc, r + 8, cc, v2, v3);
                    acc[t][j][0] = 0.0f; acc[t][j][1] = 0.0f;
                    acc[t][j][2] = 0.0f; acc[t][j][3] = 0.0f;
                }
            __syncthreads();   // H visible to partner warps
        }

        // ---- MMA over this 32-K chunk (2 k-steps of 16) ----
        #pragma unroll
        for (int ks = 0; ks < 2; ks++) {
            const uint32_t k0 = (uint32_t)(kc * 32 + ks * 16) + a_koff;
            uint32_t ah[2][4];
            #pragma unroll
            for (int t = 0; t < 2; t++) {
                uint32_t ra = (a_row + (uint32_t)(t * 16)) * A_STRIDE + k0;
                ldm_x4(ah[t], sb + A_OFF + ra * 2);
            }
            const uint32_t bk = b_base + (uint32_t)(buf * CHUNK_BYTES + ks * 32);
            #pragma unroll
            for (int jp = 0; jp < 8; jp++) {
                uint32_t bh[4];
                ldm_x4(bh, bk + (uint32_t)(jp * 1280));   // 16 n-rows * 80 B
                #pragma unroll
                for (int t = 0; t < 2; t++)
                    #pragma unroll
                    for (int jj = 0; jj < 2; jj++)
                        mma16816(acc[t][jp * 2 + jj], ah[t], bh + jj * 2);
            }
        }
    }

    // ---- epilogue 2: bias + mean over supernode (warp-local: 32 rows) ----
    #pragma unroll
    for (int j = 0; j < 16; j++) {
        float s0 = 0.0f, s1 = 0.0f;
        #pragma unroll
        for (int t = 0; t < 2; t++) {
            s0 += acc[t][j][0] + acc[t][j][2];
            s1 += acc[t][j][1] + acc[t][j][3];
        }
        #pragma unroll
        for (int off = 4; off < 32; off <<= 1) {
            s0 += __shfl_xor_sync(0xFFFFFFFFu, s0, off);
            s1 += __shfl_xor_sync(0xFFFFFFFFu, s1, off);
        }
        if (lane < 4) {
            int cc = ng * 128 + j * 8 + lane * 2;
            int s  = blockIdx.x * 4 + mg;
            float2 v;
            v.x = s0 * (1.0f / 32.0f) + b2s[cc];
            v.y = s1 * (1.0f / 32.0f) + b2s[cc + 1];
            *(float2*)&g_agg[(size_t)s * HIDDEN + cc] = v;
        }
    }
}

// ---------------------------------------------------------------------------
// Kernel 2: out = [agg | sincos(sup_pos)] @ wp + bp
// ---------------------------------------------------------------------------
#define BLK_S     64
#define AT_STRIDE 68
#define KCHUNK    32

__global__ __launch_bounds__(256, 1)
void out_proj_kernel(const float* __restrict__ pos,
                     const int* __restrict__ sup_idx,
                     const float* __restrict__ wp, const float* __restrict__ bp,
                     float* __restrict__ out) {
    extern __shared__ float smf[];
    float* At   = smf;
    float* Wb   = At + 512 * AT_STRIDE;
    float* spos = Wb + KCHUNK * 256;

    const int tid = threadIdx.x;
    const int s0  = blockIdx.x * BLK_S;

    #pragma unroll 4
    for (int r = 0; r < BLK_S; r++)
        At[tid * AT_STRIDE + r] = g_agg[(s0 + r) * HIDDEN + tid];

    if (tid < BLK_S) {
        int si = sup_idx[s0 + tid];
        spos[tid * 3 + 0] = pos[si * 3 + 0];
        spos[tid * 3 + 1] = pos[si * 3 + 1];
        spos[tid * 3 + 2] = pos[si * 3 + 2];
    }
    {
        int k = 508 + (tid >> 6);
        int r = tid & 63;
        At[k * AT_STRIDE + r] = 0.0f;
    }
    __syncthreads();

    for (int idx = tid; idx < BLK_S * 252; idx += 256) {
        int r  = idx / 252;
        int kk = idx - r * 252;
        int d  = kk / 84;
        int j  = kk - d * 84;
        int jj = (j < 42) ? j : (j - 42);
        float om = expf(-(float)jj * OM3_C);
        float v  = spos[r * 3 + d] * om;
        At[(256 + kk) * AT_STRIDE + r] = (j < 42) ? sinf(v) : cosf(v);
    }

    const int tx = tid & 31;
    const int ty = tid >> 5;
    const int r0 = ty * 8;

    float biasv[8];
    #pragma unroll
    for (int g = 0; g < 2; g++)
        #pragma unroll
        for (int u = 0; u < 4; u++) biasv[g * 4 + u] = bp[tx * 4 + g * 128 + u];

    float acc[8][8];
    #pragma unroll
    for (int i = 0; i < 8; i++)
        #pragma unroll
        for (int j = 0; j < 8; j++) acc[i][j] = 0.0f;

    for (int kt = 0; kt < 512 / KCHUNK; kt++) {
        __syncthreads();
        {
            const float4* src = (const float4*)(wp + kt * KCHUNK * 256);
            float4* dst = (float4*)Wb;
            #pragma unroll
            for (int i = 0; i < 8; i++) dst[i * 256 + tid] = src[i * 256 + tid];
        }
        __syncthreads();
        #pragma unroll 8
        for (int kk = 0; kk < KCHUNK; kk++) {
            int k = kt * KCHUNK + kk;
            float4 a0 = *(const float4*)&At[k * AT_STRIDE + r0];
            float4 a1 = *(const float4*)&At[k * AT_STRIDE + r0 + 4];
            float a[8] = {a0.x, a0.y, a0.z, a0.w, a1.x, a1.y, a1.z, a1.w};
            float b[8];
            #pragma unroll
            for (int g = 0; g < 2; g++) {
                float4 bb = *(const float4*)&Wb[kk * 256 + tx * 4 + g * 128];
                b[g * 4 + 0] = bb.x; b[g * 4 + 1] = bb.y;
                b[g * 4 + 2] = bb.z; b[g * 4 + 3] = bb.w;
            }
            #pragma unroll
            for (int i = 0; i < 8; i++)
                #pragma unroll
                for (int j = 0; j < 8; j++) acc[i][j] += a[i] * b[j];
        }
    }

    #pragma unroll
    for (int i = 0; i < 8; i++)
        #pragma unroll
        for (int g = 0; g < 2; g++) {
            float4 v;
            v.x = acc[i][g * 4 + 0] + biasv[g * 4 + 0];
            v.y = acc[i][g * 4 + 1] + biasv[g * 4 + 1];
            v.z = acc[i][g * 4 + 2] + biasv[g * 4 + 2];
            v.w = acc[i][g * 4 + 3] + biasv[g * 4 + 3];
            *(float4*)&out[(size_t)(s0 + r0 + i) * HIDDEN + tx * 4 + g * 128] = v;
        }
}

// ---------------------------------------------------------------------------
extern "C" void kernel_launch(void* const* d_in, const int* in_sizes, int n_in,
                              void* d_out, int out_size) {
    const float* pos     = (const float*)d_in[0];
    const int*   sup_idx = (const int*)d_in[1];
    const int*   src_idx = (const int*)d_in[2];
    const float* w1 = (const float*)d_in[4];
    const float* b1 = (const float*)d_in[5];
    const float* w2 = (const float*)d_in[6];
    const float* b2 = (const float*)d_in[7];
    const float* wp = (const float*)d_in[8];
    const float* bp = (const float*)d_in[9];
    float* out = (float*)d_out;

    cudaFuncSetAttribute(edge_mlp_mma,
                         cudaFuncAttributeMaxDynamicSharedMemorySize, SMEM_EDGE);
    const int smem2 = (512 * AT_STRIDE + KCHUNK * 256 + BLK_S * 3) * 4;
    cudaFuncSetAttribute(out_proj_kernel,
                         cudaFuncAttributeMaxDynamicSharedMemorySize, smem2);

    prep_weights<<<512, 256>>>(w1, w2);
    edge_mlp_mma<<<NUM_EDGES / 128, 256, SMEM_EDGE>>>(pos, sup_idx, src_idx, b1, b2);
    out_proj_kernel<<<NUM_SUP / BLK_S, 256, smem2>>>(pos, sup_idx, wp, bp, out);
}

// round 6
// speedup vs baseline: 4.3548x; 1.0616x over previous
#include <cuda_runtime.h>
#include <cuda_fp16.h>
#include <math.h>
#include <stdint.h>

#define NUM_POINTS 500000
#define NUM_SUP    8192
#define DEGREE     32
#define NUM_EDGES  (NUM_SUP * DEGREE)   // 262144
#define HIDDEN     256

#define OM4_C 0.2878231366242559f   // ln(10000)/32
#define OM3_C 0.2192938183803854f   // ln(10000)/42

// ---------------- global scratch ----------------
__device__ float g_agg[NUM_SUP * HIDDEN];
// 16 weight chunks (8 w1 + 8 w2): [chunk][256 n][32 k] fp16, zero-pad,
// XOR-swizzled 16B segs: addr_halfs = n*32 + (((k>>3) ^ ((n>>1)&3))<<3) + (k&7)
#define CHUNK_HALFS 8192
#define CHUNK_BYTES 16384
__device__ __align__(256) __half g_wc[16 * CHUNK_HALFS];

// ---------------- edge-kernel smem layout (bytes) ----------------
// A: 64 rows x 512 B (256 fp16, XOR swizzle) = 32768
#define A_OFF     0
#define BST_OFF   32768                  // 4 stages x 16384 = 65536
#define REL_OFF   98304                  // 64 x 4 float = 1024
#define B1S_OFF   99328                  // 256 float
#define B2S_OFF   100352                 // 256 float
#define MBAR_OFF  101376                 // 4 mbarriers x 8
#define SMEM_EDGE 101408

// ---------------- PTX helpers ----------------
__device__ __forceinline__ uint32_t smem_u32(const void* p) {
    uint32_t a;
    asm("{ .reg .u64 t; cvta.to.shared.u64 t, %1; cvt.u32.u64 %0, t; }" : "=r"(a) : "l"(p));
    return a;
}
__device__ __forceinline__ void ldm_x4(uint32_t* r, uint32_t addr) {
    asm volatile("ldmatrix.sync.aligned.m8n8.x4.shared.b16 {%0,%1,%2,%3}, [%4];"
                 : "=r"(r[0]), "=r"(r[1]), "=r"(r[2]), "=r"(r[3]) : "r"(addr));
}
__device__ __forceinline__ void mma16816(float* d, const uint32_t* a, const uint32_t* b) {
    asm volatile("mma.sync.aligned.m16n8k16.row.col.f32.f16.f16.f32 "
                 "{%0,%1,%2,%3}, {%4,%5,%6,%7}, {%8,%9}, {%0,%1,%2,%3};"
                 : "+f"(d[0]), "+f"(d[1]), "+f"(d[2]), "+f"(d[3])
                 : "r"(a[0]), "r"(a[1]), "r"(a[2]), "r"(a[3]), "r"(b[0]), "r"(b[1]));
}
__device__ __forceinline__ void bulk_cp(uint32_t dst, const void* src, uint32_t bytes,
                                        uint32_t mbar) {
    asm volatile("cp.async.bulk.shared::cluster.global.mbarrier::complete_tx::bytes "
                 "[%0], [%1], %2, [%3];"
                 :: "r"(dst), "l"(src), "r"(bytes), "r"(mbar) : "memory");
}
__device__ __forceinline__ void mbar_init(uint32_t mbar, uint32_t cnt) {
    asm volatile("mbarrier.init.shared.b64 [%0], %1;" :: "r"(mbar), "r"(cnt) : "memory");
}
__device__ __forceinline__ void mbar_expect(uint32_t mbar, uint32_t bytes) {
    asm volatile("mbarrier.arrive.expect_tx.shared.b64 _, [%0], %1;"
                 :: "r"(mbar), "r"(bytes) : "memory");
}
__device__ __forceinline__ void mbar_wait(uint32_t addr, int parity) {
    asm volatile(
        "{\n\t.reg .pred P;\n"
        "WL%=:\n\t"
        "mbarrier.try_wait.parity.acquire.cta.shared::cta.b64 P, [%0], %1, 0x989680;\n\t"
        "@P bra WD%=;\n\t"
        "bra WL%=;\n"
        "WD%=:\n\t}"
        :: "r"(addr), "r"(parity) : "memory");
}

// store fp16 pair at A[m][k], A[m][k+1]  (k even) with XOR swizzle
__device__ __forceinline__ void storeA(char* smc, int m, int k, float x, float y) {
    uint32_t addr = (uint32_t)(m * 512) + (uint32_t)((((k >> 3) ^ (m & 7)) << 4)) +
                    (uint32_t)((k & 7) * 2);
    *(__half2*)(smc + A_OFF + addr) = __floats2half2_rn(x, y);
}

// ---------------------------------------------------------------------------
// prep: fp16-round w[k][n], write into zero-pad swizzled chunk layout.
// ---------------------------------------------------------------------------
__global__ void prep_weights(const float* __restrict__ w1, const float* __restrict__ w2) {
    int idx = blockIdx.x * blockDim.x + threadIdx.x;   // 131072
    const float* w = (idx < 65536) ? w1 : w2;
    int base = (idx < 65536) ? 0 : 8;
    int i = idx & 65535;
    int k = i >> 8, n = i & 255;
    int chunk = base + (k >> 5);
    int kk = k & 31;
    uint32_t off = (uint32_t)(n * 32) +
                   (uint32_t)((((kk >> 3) ^ ((n >> 1) & 3)) << 3)) + (uint32_t)(kk & 7);
    g_wc[(size_t)chunk * CHUNK_HALFS + off] = __float2half_rn(w[i]);
}

// ---------------------------------------------------------------------------
// Edge kernel: 64 edges/CTA, 128 threads, 2 CTAs/SM.
// Weights streamed via cp.async.bulk (1 instr / 16KB chunk) + mbarrier.
// ---------------------------------------------------------------------------
__global__ __launch_bounds__(128, 2)
void edge_mlp_mma(const float* __restrict__ pos,
                  const int* __restrict__ sup_idx,
                  const int* __restrict__ src_idx,
                  const float* __restrict__ b1,
                  const float* __restrict__ b2) {
    extern __shared__ char smc[];
    const uint32_t sb = smem_u32(smc);
    const int tid  = threadIdx.x;
    const int wid  = tid >> 5;
    const int lane = tid & 31;
    const int mg   = wid & 1;     // rows [mg*32, mg*32+32) = supernode mg
    const int ng   = wid >> 1;    // cols [ng*128, ng*128+128)

    float* b1s = (float*)(smc + B1S_OFF);
    float* b2s = (float*)(smc + B2S_OFF);
    b1s[tid] = b1[tid];       b1s[tid + 128] = b1[tid + 128];
    b2s[tid] = b2[tid];       b2s[tid + 128] = b2[tid + 128];

    // init mbarriers + issue first 4 chunk fills (single thread)
    if (tid == 0) {
        #pragma unroll
        for (int s = 0; s < 4; s++) mbar_init(sb + MBAR_OFF + s * 8, 1);
        asm volatile("fence.proxy.async;" ::: "memory");
        #pragma unroll
        for (int s = 0; s < 4; s++) {
            mbar_expect(sb + MBAR_OFF + s * 8, CHUNK_BYTES);
            bulk_cp(sb + BST_OFF + s * CHUNK_BYTES, g_wc + (size_t)s * CHUNK_HALFS,
                    CHUNK_BYTES, sb + MBAR_OFF + s * 8);
        }
    }

    // ---- relative positions (64 edges) ----
    if (tid < 64) {
        int e = blockIdx.x * 64 + tid;
        int si = sup_idx[e >> 5], sr = src_idx[e];
        float dx = pos[si * 3 + 0] - pos[sr * 3 + 0];
        float dy = pos[si * 3 + 1] - pos[sr * 3 + 1];
        float dz = pos[si * 3 + 2] - pos[sr * 3 + 2];
        float* rb = (float*)(smc + REL_OFF);
        rb[tid * 4 + 0] = dx; rb[tid * 4 + 1] = dy; rb[tid * 4 + 2] = dz;
        rb[tid * 4 + 3] = sqrtf(dx * dx + dy * dy + dz * dz);
    }
    __syncthreads();   // rel + mbarrier init visible

    // ---- sincos embed -> A fp16 (thread: row m=tid&63, half h=tid>>6) ----
    {
        const float* rb = (const float*)(smc + REL_OFF);
        int m = tid & 63, h = tid >> 6;
        float r2 = rb[m * 4 + h * 2], r3 = rb[m * 4 + h * 2 + 1];
        #pragma unroll 4
        for (int j = 0; j < 64; j += 2) {
            int jj = j & 31;
            float om0 = __expf(-(float)jj * OM4_C);
            float om1 = __expf(-(float)(jj + 1) * OM4_C);
            float a0 = r2 * om0, a1 = r2 * om1;
            float c0 = r3 * om0, c1 = r3 * om1;
            if (j < 32) {
                storeA(smc, m, (h * 2) * 64 + j,     __sinf(a0), __sinf(a1));
                storeA(smc, m, (h * 2 + 1) * 64 + j, __sinf(c0), __sinf(c1));
            } else {
                storeA(smc, m, (h * 2) * 64 + j,     __cosf(a0), __cosf(a1));
                storeA(smc, m, (h * 2 + 1) * 64 + j, __cosf(c0), __cosf(c1));
            }
        }
    }
    __syncthreads();   // A ready for all warps

    float acc[2][16][4];
    #pragma unroll
    for (int t = 0; t < 2; t++)
        #pragma unroll
        for (int j = 0; j < 16; j++)
            #pragma unroll
            for (int q = 0; q < 4; q++) acc[t][j][q] = 0.0f;

    // A lane bases: x4 = 16 rows x 2 k-halves
    const uint32_t a_row = (uint32_t)(mg * 32 + (lane & 15));
    const int akh  = (lane >> 4);            // k-half within 16-k step
    const int aswz = lane & 7;               // row swizzle bits (a_row & 7)
    // B lane bases: x4 over an n-tile pair = 16 n-rows x 2 k-halves
    const int bn   = (lane & 7) | (((lane >> 4) & 1) << 3);  // 0..15
    const int bkh  = (lane >> 3) & 1;
    const int gswz = (bn >> 1) & 3;
    const uint32_t bno = (uint32_t)((ng * 128 + bn) * 64);
    const uint32_t boff0 = bno + (uint32_t)(((bkh)     ^ gswz) << 4);  // ks=0
    const uint32_t boff1 = bno + (uint32_t)(((2 + bkh) ^ gswz) << 4);  // ks=1

    const int l4 = lane >> 2;
    const int l2 = (lane & 3) * 2;

    #pragma unroll 1
    for (int c = 0; c < 16; c++) {
        const int slot = c & 3;
        const int kc   = c & 7;
        const int par  = (c >> 2) & 1;

        if (c == 8) {
            // ---- epilogue 1: bias + exact GELU -> rewrite A (fp16) ----
            #pragma unroll
            for (int t = 0; t < 2; t++)
                #pragma unroll
                for (int j = 0; j < 16; j++) {
                    int r  = mg * 32 + t * 16 + l4;
                    int cc = ng * 128 + j * 8 + l2;
                    float v0 = acc[t][j][0] + b1s[cc];
                    float v1 = acc[t][j][1] + b1s[cc + 1];
                    float v2 = acc[t][j][2] + b1s[cc];
                    float v3 = acc[t][j][3] + b1s[cc + 1];
                    v0 = 0.5f * v0 * (1.0f + erff(v0 * 0.70710678f));
                    v1 = 0.5f * v1 * (1.0f + erff(v1 * 0.70710678f));
                    v2 = 0.5f * v2 * (1.0f + erff(v2 * 0.70710678f));
                    v3 = 0.5f * v3 * (1.0f + erff(v3 * 0.70710678f));
                    storeA(smc, r,     cc, v0, v1);
                    storeA(smc, r + 8, cc, v2, v3);
                    acc[t][j][0] = 0.0f; acc[t][j][1] = 0.0f;
                    acc[t][j][2] = 0.0f; acc[t][j][3] = 0.0f;
                }
            __syncthreads();   // H visible to partner warps
        }

        mbar_wait(sb + MBAR_OFF + slot * 8, par);   // chunk data + visibility

        // ---- MMA over this 32-K chunk (2 k-steps of 16) ----
        const uint32_t stg = sb + BST_OFF + (uint32_t)(slot * CHUNK_BYTES);
        #pragma unroll
        for (int ks = 0; ks < 2; ks++) {
            uint32_t ah[2][4];
            const int seg = kc * 4 + ks * 2 + akh;
            const uint32_t aoff = (uint32_t)(((seg ^ aswz) << 4));
            #pragma unroll
            for (int t = 0; t < 2; t++)
                ldm_x4(ah[t], sb + A_OFF + (a_row + (uint32_t)(t * 16)) * 512 + aoff);
            const uint32_t bk = stg + (ks ? boff1 : boff0);
            #pragma unroll
            for (int jp = 0; jp < 8; jp++) {
                uint32_t bh[4];
                ldm_x4(bh, bk + (uint32_t)(jp * 1024));   // 16 n-rows * 64 B
                #pragma unroll
                for (int t = 0; t < 2; t++)
                    #pragma unroll
                    for (int jj = 0; jj < 2; jj++)
                        mma16816(acc[t][jp * 2 + jj], ah[t], bh + jj * 2);
            }
        }

        __syncthreads();   // all warps done with this slot
        if (tid == 0 && c < 12) {
            mbar_expect(sb + MBAR_OFF + slot * 8, CHUNK_BYTES);
            bulk_cp(sb + BST_OFF + slot * CHUNK_BYTES,
                    g_wc + (size_t)(c + 4) * CHUNK_HALFS,
                    CHUNK_BYTES, sb + MBAR_OFF + slot * 8);
        }
    }

    // ---- epilogue 2: bias + mean over supernode (warp-local: 32 rows) ----
    #pragma unroll
    for (int j = 0; j < 16; j++) {
        float s0 = 0.0f, s1 = 0.0f;
        #pragma unroll
        for (int t = 0; t < 2; t++) {
            s0 += acc[t][j][0] + acc[t][j][2];
            s1 += acc[t][j][1] + acc[t][j][3];
        }
        #pragma unroll
        for (int off = 4; off < 32; off <<= 1) {
            s0 += __shfl_xor_sync(0xFFFFFFFFu, s0, off);
            s1 += __shfl_xor_sync(0xFFFFFFFFu, s1, off);
        }
        if (lane < 4) {
            int cc = ng * 128 + j * 8 + lane * 2;
            int s  = blockIdx.x * 2 + mg;
            float2 v;
            v.x = s0 * (1.0f / 32.0f) + b2s[cc];
            v.y = s1 * (1.0f / 32.0f) + b2s[cc + 1];
            *(float2*)&g_agg[(size_t)s * HIDDEN + cc] = v;
        }
    }
}

// ---------------------------------------------------------------------------
// Kernel 2: out = [agg | sincos(sup_pos)] @ wp + bp
// ---------------------------------------------------------------------------
#define BLK_S     64
#define AT_STRIDE 68
#define KCHUNK    32

__global__ __launch_bounds__(256, 1)
void out_proj_kernel(const float* __restrict__ pos,
                     const int* __restrict__ sup_idx,
                     const float* __restrict__ wp, const float* __restrict__ bp,
                     float* __restrict__ out) {
    extern __shared__ float smf[];
    float* At   = smf;
    float* Wb   = At + 512 * AT_STRIDE;
    float* spos = Wb + KCHUNK * 256;

    const int tid = threadIdx.x;
    const int s0  = blockIdx.x * BLK_S;

    #pragma unroll 4
    for (int r = 0; r < BLK_S; r++)
        At[tid * AT_STRIDE + r] = g_agg[(s0 + r) * HIDDEN + tid];

    if (tid < BLK_S) {
        int si = sup_idx[s0 + tid];
        spos[tid * 3 + 0] = pos[si * 3 + 0];
        spos[tid * 3 + 1] = pos[si * 3 + 1];
        spos[tid * 3 + 2] = pos[si * 3 + 2];
    }
    {
        int k = 508 + (tid >> 6);
        int r = tid & 63;
        At[k * AT_STRIDE + r] = 0.0f;
    }
    __syncthreads();

    for (int idx = tid; idx < BLK_S * 252; idx += 256) {
        int r  = idx / 252;
        int kk = idx - r * 252;
        int d  = kk / 84;
        int j  = kk - d * 84;
        int jj = (j < 42) ? j : (j - 42);
        float om = expf(-(float)jj * OM3_C);
        float v  = spos[r * 3 + d] * om;
        At[(256 + kk) * AT_STRIDE + r] = (j < 42) ? sinf(v) : cosf(v);
    }

    const int tx = tid & 31;
    const int ty = tid >> 5;
    const int r0 = ty * 8;

    float biasv[8];
    #pragma unroll
    for (int g = 0; g < 2; g++)
        #pragma unroll
        for (int u = 0; u < 4; u++) biasv[g * 4 + u] = bp[tx * 4 + g * 128 + u];

    float acc[8][8];
    #pragma unroll
    for (int i = 0; i < 8; i++)
        #pragma unroll
        for (int j = 0; j < 8; j++) acc[i][j] = 0.0f;

    for (int kt = 0; kt < 512 / KCHUNK; kt++) {
        __syncthreads();
        {
            const float4* src = (const float4*)(wp + kt * KCHUNK * 256);
            float4* dst = (float4*)Wb;
            #pragma unroll
            for (int i = 0; i < 8; i++) dst[i * 256 + tid] = src[i * 256 + tid];
        }
        __syncthreads();
        #pragma unroll 8
        for (int kk = 0; kk < KCHUNK; kk++) {
            int k = kt * KCHUNK + kk;
            float4 a0 = *(const float4*)&At[k * AT_STRIDE + r0];
            float4 a1 = *(const float4*)&At[k * AT_STRIDE + r0 + 4];
            float a[8] = {a0.x, a0.y, a0.z, a0.w, a1.x, a1.y, a1.z, a1.w};
            float b[8];
            #pragma unroll
            for (int g = 0; g < 2; g++) {
                float4 bb = *(const float4*)&Wb[kk * 256 + tx * 4 + g * 128];
                b[g * 4 + 0] = bb.x; b[g * 4 + 1] = bb.y;
                b[g * 4 + 2] = bb.z; b[g * 4 + 3] = bb.w;
            }
            #pragma unroll
            for (int i = 0; i < 8; i++)
                #pragma unroll
                for (int j = 0; j < 8; j++) acc[i][j] += a[i] * b[j];
        }
    }

    #pragma unroll
    for (int i = 0; i < 8; i++)
        #pragma unroll
        for (int g = 0; g < 2; g++) {
            float4 v;
            v.x = acc[i][g * 4 + 0] + biasv[g * 4 + 0];
            v.y = acc[i][g * 4 + 1] + biasv[g * 4 + 1];
            v.z = acc[i][g * 4 + 2] + biasv[g * 4 + 2];
            v.w = acc[i][g * 4 + 3] + biasv[g * 4 + 3];
            *(float4*)&out[(size_t)(s0 + r0 + i) * HIDDEN + tx * 4 + g * 128] = v;
        }
}

// ---------------------------------------------------------------------------
extern "C" void kernel_launch(void* const* d_in, const int* in_sizes, int n_in,
                              void* d_out, int out_size) {
    const float* pos     = (const float*)d_in[0];
    const int*   sup_idx = (const int*)d_in[1];
    const int*   src_idx = (const int*)d_in[2];
    const float* w1 = (const float*)d_in[4];
    const float* b1 = (const float*)d_in[5];
    const float* w2 = (const float*)d_in[6];
    const float* b2 = (const float*)d_in[7];
    const float* wp = (const float*)d_in[8];
    const float* bp = (const float*)d_in[9];
    float* out = (float*)d_out;

    cudaFuncSetAttribute(edge_mlp_mma,
                         cudaFuncAttributeMaxDynamicSharedMemorySize, SMEM_EDGE);
    const int smem2 = (512 * AT_STRIDE + KCHUNK * 256 + BLK_S * 3) * 4;
    cudaFuncSetAttribute(out_proj_kernel,
                         cudaFuncAttributeMaxDynamicSharedMemorySize, smem2);

    prep_weights<<<512, 256>>>(w1, w2);
    edge_mlp_mma<<<NUM_EDGES / 64, 128, SMEM_EDGE>>>(pos, sup_idx, src_idx, b1, b2);
    out_proj_kernel<<<NUM_SUP / BLK_S, 256, smem2>>>(pos, sup_idx, wp, bp, out);
}

// round 7
// speedup vs baseline: 4.3605x; 1.0013x over previous
#include <cuda_runtime.h>
#include <cuda_fp16.h>
#include <math.h>
#include <stdint.h>

#define NUM_POINTS 500000
#define NUM_SUP    8192
#define DEGREE     32
#define NUM_EDGES  (NUM_SUP * DEGREE)   // 262144
#define HIDDEN     256

#define OM4_C 0.2878231366242559f   // ln(10000)/32
#define OM3_C 0.2192938183803854f   // ln(10000)/42

// ---------------- global scratch ----------------
__device__ float g_agg[NUM_SUP * HIDDEN];
// 16 weight chunks (8 w1 + 8 w2): [chunk][256 n][32 k] fp16, zero-pad,
// XOR-swizzled 16B segs: addr_halfs = n*32 + (((k>>3) ^ ((n>>1)&3))<<3) + (k&7)
#define CHUNK_HALFS 8192
#define CHUNK_BYTES 16384
__device__ __align__(256) __half g_wc[16 * CHUNK_HALFS];

// ---------------- edge-kernel smem layout (bytes) ----------------
// A: 64 rows x 512 B (256 fp16, XOR swizzle) = 32768
#define A_OFF     0
#define BST_OFF   32768                  // 4 stages x 16384 = 65536
#define REL_OFF   98304                  // 64 x 4 float = 1024
#define B1S_OFF   99328                  // 256 float
#define B2S_OFF   100352                 // 256 float
#define MBAR_OFF  101376                 // 4 mbarriers x 8
#define SMEM_EDGE 101408

// ---------------- PTX helpers ----------------
__device__ __forceinline__ uint32_t smem_u32(const void* p) {
    uint32_t a;
    asm("{ .reg .u64 t; cvta.to.shared.u64 t, %1; cvt.u32.u64 %0, t; }" : "=r"(a) : "l"(p));
    return a;
}
__device__ __forceinline__ void ldm_x4(uint32_t* r, uint32_t addr) {
    asm volatile("ldmatrix.sync.aligned.m8n8.x4.shared.b16 {%0,%1,%2,%3}, [%4];"
                 : "=r"(r[0]), "=r"(r[1]), "=r"(r[2]), "=r"(r[3]) : "r"(addr));
}
__device__ __forceinline__ void mma16816(float* d, const uint32_t* a, const uint32_t* b) {
    asm volatile("mma.sync.aligned.m16n8k16.row.col.f32.f16.f16.f32 "
                 "{%0,%1,%2,%3}, {%4,%5,%6,%7}, {%8,%9}, {%0,%1,%2,%3};"
                 : "+f"(d[0]), "+f"(d[1]), "+f"(d[2]), "+f"(d[3])
                 : "r"(a[0]), "r"(a[1]), "r"(a[2]), "r"(a[3]), "r"(b[0]), "r"(b[1]));
}
__device__ __forceinline__ void bulk_cp(uint32_t dst, const void* src, uint32_t bytes,
                                        uint32_t mbar) {
    asm volatile("cp.async.bulk.shared::cluster.global.mbarrier::complete_tx::bytes "
                 "[%0], [%1], %2, [%3];"
                 :: "r"(dst), "l"(src), "r"(bytes), "r"(mbar) : "memory");
}
__device__ __forceinline__ void mbar_init(uint32_t mbar, uint32_t cnt) {
    asm volatile("mbarrier.init.shared.b64 [%0], %1;" :: "r"(mbar), "r"(cnt) : "memory");
}
__device__ __forceinline__ void mbar_expect(uint32_t mbar, uint32_t bytes) {
    asm volatile("mbarrier.arrive.expect_tx.shared.b64 _, [%0], %1;"
                 :: "r"(mbar), "r"(bytes) : "memory");
}
__device__ __forceinline__ void mbar_wait(uint32_t addr, int parity) {
    asm volatile(
        "{\n\t.reg .pred P;\n"
        "WL%=:\n\t"
        "mbarrier.try_wait.parity.acquire.cta.shared::cta.b64 P, [%0], %1, 0x989680;\n\t"
        "@P bra WD%=;\n\t"
        "bra WL%=;\n"
        "WD%=:\n\t}"
        :: "r"(addr), "r"(parity) : "memory");
}

// store fp16 pair at A[m][k], A[m][k+1]  (k even) with XOR swizzle
__device__ __forceinline__ void storeA(char* smc, int m, int k, float x, float y) {
    uint32_t addr = (uint32_t)(m * 512) + (uint32_t)((((k >> 3) ^ (m & 7)) << 4)) +
                    (uint32_t)((k & 7) * 2);
    *(__half2*)(smc + A_OFF + addr) = __floats2half2_rn(x, y);
}

// ---------------------------------------------------------------------------
// prep: fp16-round w[k][n], write into zero-pad swizzled chunk layout.
// ---------------------------------------------------------------------------
__global__ void prep_weights(const float* __restrict__ w1, const float* __restrict__ w2) {
    int idx = blockIdx.x * blockDim.x + threadIdx.x;   // 131072
    const float* w = (idx < 65536) ? w1 : w2;
    int base = (idx < 65536) ? 0 : 8;
    int i = idx & 65535;
    int k = i >> 8, n = i & 255;
    int chunk = base + (k >> 5);
    int kk = k & 31;
    uint32_t off = (uint32_t)(n * 32) +
                   (uint32_t)((((kk >> 3) ^ ((n >> 1) & 3)) << 3)) + (uint32_t)(kk & 7);
    g_wc[(size_t)chunk * CHUNK_HALFS + off] = __float2half_rn(w[i]);
}

// ---------------------------------------------------------------------------
// Edge kernel: 64 edges/CTA, 128 threads, 2 CTAs/SM.
// Weights streamed via cp.async.bulk (1 instr / 16KB chunk) + mbarrier.
// ---------------------------------------------------------------------------
__global__ __launch_bounds__(128, 2)
void edge_mlp_mma(const float* __restrict__ pos,
                  const int* __restrict__ sup_idx,
                  const int* __restrict__ src_idx,
                  const float* __restrict__ b1,
                  const float* __restrict__ b2) {
    extern __shared__ char smc[];
    const uint32_t sb = smem_u32(smc);
    const int tid  = threadIdx.x;
    const int wid  = tid >> 5;
    const int lane = tid & 31;
    const int mg   = wid & 1;     // rows [mg*32, mg*32+32) = supernode mg
    const int ng   = wid >> 1;    // cols [ng*128, ng*128+128)

    float* b1s = (float*)(smc + B1S_OFF);
    float* b2s = (float*)(smc + B2S_OFF);
    b1s[tid] = b1[tid];       b1s[tid + 128] = b1[tid + 128];
    b2s[tid] = b2[tid];       b2s[tid + 128] = b2[tid + 128];

    // init mbarriers + issue first 4 chunk fills (single thread)
    if (tid == 0) {
        #pragma unroll
        for (int s = 0; s < 4; s++) mbar_init(sb + MBAR_OFF + s * 8, 1);
        asm volatile("fence.proxy.async;" ::: "memory");
        #pragma unroll
        for (int s = 0; s < 4; s++) {
            mbar_expect(sb + MBAR_OFF + s * 8, CHUNK_BYTES);
            bulk_cp(sb + BST_OFF + s * CHUNK_BYTES, g_wc + (size_t)s * CHUNK_HALFS,
                    CHUNK_BYTES, sb + MBAR_OFF + s * 8);
        }
    }

    // ---- relative positions (64 edges) ----
    if (tid < 64) {
        int e = blockIdx.x * 64 + tid;
        int si = sup_idx[e >> 5], sr = src_idx[e];
        float dx = pos[si * 3 + 0] - pos[sr * 3 + 0];
        float dy = pos[si * 3 + 1] - pos[sr * 3 + 1];
        float dz = pos[si * 3 + 2] - pos[sr * 3 + 2];
        float* rb = (float*)(smc + REL_OFF);
        rb[tid * 4 + 0] = dx; rb[tid * 4 + 1] = dy; rb[tid * 4 + 2] = dz;
        rb[tid * 4 + 3] = sqrtf(dx * dx + dy * dy + dz * dz);
    }
    __syncthreads();   // rel + mbarrier init visible

    // ---- sincos embed -> A fp16 (thread: row m=tid&63, half h=tid>>6) ----
    {
        const float* rb = (const float*)(smc + REL_OFF);
        int m = tid & 63, h = tid >> 6;
        float r2 = rb[m * 4 + h * 2], r3 = rb[m * 4 + h * 2 + 1];
        #pragma unroll 4
        for (int j = 0; j < 64; j += 2) {
            int jj = j & 31;
            float om0 = __expf(-(float)jj * OM4_C);
            float om1 = __expf(-(float)(jj + 1) * OM4_C);
            float a0 = r2 * om0, a1 = r2 * om1;
            float c0 = r3 * om0, c1 = r3 * om1;
            if (j < 32) {
                storeA(smc, m, (h * 2) * 64 + j,     __sinf(a0), __sinf(a1));
                storeA(smc, m, (h * 2 + 1) * 64 + j, __sinf(c0), __sinf(c1));
            } else {
                storeA(smc, m, (h * 2) * 64 + j,     __cosf(a0), __cosf(a1));
                storeA(smc, m, (h * 2 + 1) * 64 + j, __cosf(c0), __cosf(c1));
            }
        }
    }
    __syncthreads();   // A ready for all warps

    float acc[2][16][4];
    #pragma unroll
    for (int t = 0; t < 2; t++)
        #pragma unroll
        for (int j = 0; j < 16; j++)
            #pragma unroll
            for (int q = 0; q < 4; q++) acc[t][j][q] = 0.0f;

    // A lane bases: x4 = 16 rows x 2 k-halves
    const uint32_t a_row = (uint32_t)(mg * 32 + (lane & 15));
    const int akh  = (lane >> 4);            // k-half within 16-k step
    const int aswz = lane & 7;               // row swizzle bits (a_row & 7)
    // B lane bases: x4 over an n-tile pair = 16 n-rows x 2 k-halves
    const int bn   = (lane & 7) | (((lane >> 4) & 1) << 3);  // 0..15
    const int bkh  = (lane >> 3) & 1;
    const int gswz = (bn >> 1) & 3;
    const uint32_t bno = (uint32_t)((ng * 128 + bn) * 64);
    const uint32_t boff0 = bno + (uint32_t)(((bkh)     ^ gswz) << 4);  // ks=0
    const uint32_t boff1 = bno + (uint32_t)(((2 + bkh) ^ gswz) << 4);  // ks=1

    const int l4 = lane >> 2;
    const int l2 = (lane & 3) * 2;

    #pragma unroll 1
    for (int c = 0; c < 16; c++) {
        const int slot = c & 3;
        const int kc   = c & 7;
        const int par  = (c >> 2) & 1;

        if (c == 8) {
            // ---- epilogue 1: bias + exact GELU -> rewrite A (fp16) ----
            #pragma unroll
            for (int t = 0; t < 2; t++)
                #pragma unroll
                for (int j = 0; j < 16; j++) {
                    int r  = mg * 32 + t * 16 + l4;
                    int cc = ng * 128 + j * 8 + l2;
                    float v0 = acc[t][j][0] + b1s[cc];
                    float v1 = acc[t][j][1] + b1s[cc + 1];
                    float v2 = acc[t][j][2] + b1s[cc];
                    float v3 = acc[t][j][3] + b1s[cc + 1];
                    v0 = 0.5f * v0 * (1.0f + erff(v0 * 0.70710678f));
                    v1 = 0.5f * v1 * (1.0f + erff(v1 * 0.70710678f));
                    v2 = 0.5f * v2 * (1.0f + erff(v2 * 0.70710678f));
                    v3 = 0.5f * v3 * (1.0f + erff(v3 * 0.70710678f));
                    storeA(smc, r,     cc, v0, v1);
                    storeA(smc, r + 8, cc, v2, v3);
                    acc[t][j][0] = 0.0f; acc[t][j][1] = 0.0f;
                    acc[t][j][2] = 0.0f; acc[t][j][3] = 0.0f;
                }
            __syncthreads();   // H visible to partner warps
        }

        mbar_wait(sb + MBAR_OFF + slot * 8, par);   // chunk data + visibility

        // ---- MMA over this 32-K chunk (2 k-steps of 16) ----
        const uint32_t stg = sb + BST_OFF + (uint32_t)(slot * CHUNK_BYTES);
        #pragma unroll
        for (int ks = 0; ks < 2; ks++) {
            uint32_t ah[2][4];
            const int seg = kc * 4 + ks * 2 + akh;
            const uint32_t aoff = (uint32_t)(((seg ^ aswz) << 4));
            #pragma unroll
            for (int t = 0; t < 2; t++)
                ldm_x4(ah[t], sb + A_OFF + (a_row + (uint32_t)(t * 16)) * 512 + aoff);
            const uint32_t bk = stg + (ks ? boff1 : boff0);
            #pragma unroll
            for (int jp = 0; jp < 8; jp++) {
                uint32_t bh[4];
                ldm_x4(bh, bk + (uint32_t)(jp * 1024));   // 16 n-rows * 64 B
                #pragma unroll
                for (int t = 0; t < 2; t++)
                    #pragma unroll
                    for (int jj = 0; jj < 2; jj++)
                        mma16816(acc[t][jp * 2 + jj], ah[t], bh + jj * 2);
            }
        }

        __syncthreads();   // all warps done with this slot
        if (tid == 0 && c < 12) {
            mbar_expect(sb + MBAR_OFF + slot * 8, CHUNK_BYTES);
            bulk_cp(sb + BST_OFF + slot * CHUNK_BYTES,
                    g_wc + (size_t)(c + 4) * CHUNK_HALFS,
                    CHUNK_BYTES, sb + MBAR_OFF + slot * 8);
        }
    }

    // ---- epilogue 2: bias + mean over supernode (warp-local: 32 rows) ----
    #pragma unroll
    for (int j = 0; j < 16; j++) {
        float s0 = 0.0f, s1 = 0.0f;
        #pragma unroll
        for (int t = 0; t < 2; t++) {
            s0 += acc[t][j][0] + acc[t][j][2];
            s1 += acc[t][j][1] + acc[t][j][3];
        }
        #pragma unroll
        for (int off = 4; off < 32; off <<= 1) {
            s0 += __shfl_xor_sync(0xFFFFFFFFu, s0, off);
            s1 += __shfl_xor_sync(0xFFFFFFFFu, s1, off);
        }
        if (lane < 4) {
            int cc = ng * 128 + j * 8 + lane * 2;
            int s  = blockIdx.x * 2 + mg;
            float2 v;
            v.x = s0 * (1.0f / 32.0f) + b2s[cc];
            v.y = s1 * (1.0f / 32.0f) + b2s[cc + 1];
            *(float2*)&g_agg[(size_t)s * HIDDEN + cc] = v;
        }
    }
}

// ---------------------------------------------------------------------------
// Kernel 2: out = [agg | sincos(sup_pos)] @ wp + bp
// ---------------------------------------------------------------------------
#define BLK_S     64
#define AT_STRIDE 68
#define KCHUNK    32

__global__ __launch_bounds__(256, 1)
void out_proj_kernel(const float* __restrict__ pos,
                     const int* __restrict__ sup_idx,
                     const float* __restrict__ wp, const float* __restrict__ bp,
                     float* __restrict__ out) {
    extern __shared__ float smf[];
    float* At   = smf;
    float* Wb   = At + 512 * AT_STRIDE;
    float* spos = Wb + KCHUNK * 256;

    const int tid = threadIdx.x;
    const int s0  = blockIdx.x * BLK_S;

    #pragma unroll 4
    for (int r = 0; r < BLK_S; r++)
        At[tid * AT_STRIDE + r] = g_agg[(s0 + r) * HIDDEN + tid];

    if (tid < BLK_S) {
        int si = sup_idx[s0 + tid];
        spos[tid * 3 + 0] = pos[si * 3 + 0];
        spos[tid * 3 + 1] = pos[si * 3 + 1];
        spos[tid * 3 + 2] = pos[si * 3 + 2];
    }
    {
        int k = 508 + (tid >> 6);
        int r = tid & 63;
        At[k * AT_STRIDE + r] = 0.0f;
    }
    __syncthreads();

    for (int idx = tid; idx < BLK_S * 252; idx += 256) {
        int r  = idx / 252;
        int kk = idx - r * 252;
        int d  = kk / 84;
        int j  = kk - d * 84;
        int jj = (j < 42) ? j : (j - 42);
        float om = expf(-(float)jj * OM3_C);
        float v  = spos[r * 3 + d] * om;
        At[(256 + kk) * AT_STRIDE + r] = (j < 42) ? sinf(v) : cosf(v);
    }

    const int tx = tid & 31;
    const int ty = tid >> 5;
    const int r0 = ty * 8;

    float biasv[8];
    #pragma unroll
    for (int g = 0; g < 2; g++)
        #pragma unroll
        for (int u = 0; u < 4; u++) biasv[g * 4 + u] = bp[tx * 4 + g * 128 + u];

    float acc[8][8];
    #pragma unroll
    for (int i = 0; i < 8; i++)
        #pragma unroll
        for (int j = 0; j < 8; j++) acc[i][j] = 0.0f;

    for (int kt = 0; kt < 512 / KCHUNK; kt++) {
        __syncthreads();
        {
            const float4* src = (const float4*)(wp + kt * KCHUNK * 256);
            float4* dst = (float4*)Wb;
            #pragma unroll
            for (int i = 0; i < 8; i++) dst[i * 256 + tid] = src[i * 256 + tid];
        }
        __syncthreads();
        #pragma unroll 8
        for (int kk = 0; kk < KCHUNK; kk++) {
            int k = kt * KCHUNK + kk;
            float4 a0 = *(const float4*)&At[k * AT_STRIDE + r0];
            float4 a1 = *(const float4*)&At[k * AT_STRIDE + r0 + 4];
            float a[8] = {a0.x, a0.y, a0.z, a0.w, a1.x, a1.y, a1.z, a1.w};
            float b[8];
            #pragma unroll
            for (int g = 0; g < 2; g++) {
                float4 bb = *(const float4*)&Wb[kk * 256 + tx * 4 + g * 128];
                b[g * 4 + 0] = bb.x; b[g * 4 + 1] = bb.y;
                b[g * 4 + 2] = bb.z; b[g * 4 + 3] = bb.w;
            }
            #pragma unroll
            for (int i = 0; i < 8; i++)
                #pragma unroll
                for (int j = 0; j < 8; j++) acc[i][j] += a[i] * b[j];
        }
    }

    #pragma unroll
    for (int i = 0; i < 8; i++)
        #pragma unroll
        for (int g = 0; g < 2; g++) {
            float4 v;
            v.x = acc[i][g * 4 + 0] + biasv[g * 4 + 0];
            v.y = acc[i][g * 4 + 1] + biasv[g * 4 + 1];
            v.z = acc[i][g * 4 + 2] + biasv[g * 4 + 2];
            v.w = acc[i][g * 4 + 3] + biasv[g * 4 + 3];
            *(float4*)&out[(size_t)(s0 + r0 + i) * HIDDEN + tx * 4 + g * 128] = v;
        }
}

// ---------------------------------------------------------------------------
extern "C" void kernel_launch(void* const* d_in, const int* in_sizes, int n_in,
                              void* d_out, int out_size) {
    const float* pos     = (const float*)d_in[0];
    const int*   sup_idx = (const int*)d_in[1];
    const int*   src_idx = (const int*)d_in[2];
    const float* w1 = (const float*)d_in[4];
    const float* b1 = (const float*)d_in[5];
    const float* w2 = (const float*)d_in[6];
    const float* b2 = (const float*)d_in[7];
    const float* wp = (const float*)d_in[8];
    const float* bp = (const float*)d_in[9];
    float* out = (float*)d_out;

    cudaFuncSetAttribute(edge_mlp_mma,
                         cudaFuncAttributeMaxDynamicSharedMemorySize, SMEM_EDGE);
    const int smem2 = (512 * AT_STRIDE + KCHUNK * 256 + BLK_S * 3) * 4;
    cudaFuncSetAttribute(out_proj_kernel,
                         cudaFuncAttributeMaxDynamicSharedMemorySize, smem2);

    prep_weights<<<512, 256>>>(w1, w2);
    edge_mlp_mma<<<NUM_EDGES / 64, 128, SMEM_EDGE>>>(pos, sup_idx, src_idx, b1, b2);
    out_proj_kernel<<<NUM_SUP / BLK_S, 256, smem2>>>(pos, sup_idx, wp, bp, out);
}

// round 8
// speedup vs baseline: 4.3612x; 1.0002x over previous
#include <cuda_runtime.h>
#include <cuda_fp16.h>
#include <math.h>
#include <stdint.h>

#define NUM_POINTS 500000
#define NUM_SUP    8192
#define DEGREE     32
#define NUM_EDGES  (NUM_SUP * DEGREE)   // 262144
#define HIDDEN     256

#define OM4_C 0.2878231366242559f   // ln(10000)/32
#define OM3_C 0.2192938183803854f   // ln(10000)/42

// ---------------- global scratch ----------------
__device__ float g_agg[NUM_SUP * HIDDEN];
// 16 weight chunks (8 w1 + 8 w2): [chunk][256 n][32 k] fp16, zero-pad,
// XOR-swizzled 16B segs: addr_halfs = n*32 + (((k>>3) ^ ((n>>1)&3))<<3) + (k&7)
#define CHUNK_HALFS 8192
#define CHUNK_BYTES 16384
__device__ __align__(256) __half g_wc[16 * CHUNK_HALFS];

// ---------------- edge-kernel smem layout (bytes) ----------------
// A: 64 rows x 512 B (256 fp16, XOR swizzle) = 32768
#define A_OFF     0
#define BST_OFF   32768                  // 4 stages x 16384 = 65536
#define REL_OFF   98304                  // 64 x 4 float = 1024
#define B1S_OFF   99328                  // 256 float
#define B2S_OFF   100352                 // 256 float
#define MBAR_OFF  101376                 // 4 mbarriers x 8
#define SMEM_EDGE 101408

// ---------------- PTX helpers ----------------
__device__ __forceinline__ uint32_t smem_u32(const void* p) {
    uint32_t a;
    asm("{ .reg .u64 t; cvta.to.shared.u64 t, %1; cvt.u32.u64 %0, t; }" : "=r"(a) : "l"(p));
    return a;
}
__device__ __forceinline__ void ldm_x4(uint32_t* r, uint32_t addr) {
    asm volatile("ldmatrix.sync.aligned.m8n8.x4.shared.b16 {%0,%1,%2,%3}, [%4];"
                 : "=r"(r[0]), "=r"(r[1]), "=r"(r[2]), "=r"(r[3]) : "r"(addr));
}
__device__ __forceinline__ void mma16816(float* d, const uint32_t* a, const uint32_t* b) {
    asm volatile("mma.sync.aligned.m16n8k16.row.col.f32.f16.f16.f32 "
                 "{%0,%1,%2,%3}, {%4,%5,%6,%7}, {%8,%9}, {%0,%1,%2,%3};"
                 : "+f"(d[0]), "+f"(d[1]), "+f"(d[2]), "+f"(d[3])
                 : "r"(a[0]), "r"(a[1]), "r"(a[2]), "r"(a[3]), "r"(b[0]), "r"(b[1]));
}
__device__ __forceinline__ void bulk_cp(uint32_t dst, const void* src, uint32_t bytes,
                                        uint32_t mbar) {
    asm volatile("cp.async.bulk.shared::cluster.global.mbarrier::complete_tx::bytes "
                 "[%0], [%1], %2, [%3];"
                 :: "r"(dst), "l"(src), "r"(bytes), "r"(mbar) : "memory");
}
__device__ __forceinline__ void mbar_init(uint32_t mbar, uint32_t cnt) {
    asm volatile("mbarrier.init.shared.b64 [%0], %1;" :: "r"(mbar), "r"(cnt) : "memory");
}
__device__ __forceinline__ void mbar_expect(uint32_t mbar, uint32_t bytes) {
    asm volatile("mbarrier.arrive.expect_tx.shared.b64 _, [%0], %1;"
                 :: "r"(mbar), "r"(bytes) : "memory");
}
__device__ __forceinline__ void mbar_wait(uint32_t addr, int parity) {
    asm volatile(
        "{\n\t.reg .pred P;\n"
        "WL%=:\n\t"
        "mbarrier.try_wait.parity.acquire.cta.shared::cta.b64 P, [%0], %1, 0x989680;\n\t"
        "@P bra WD%=;\n\t"
        "bra WL%=;\n"
        "WD%=:\n\t}"
        :: "r"(addr), "r"(parity) : "memory");
}

// store fp16 pair at A[m][k], A[m][k+1]  (k even) with XOR swizzle
__device__ __forceinline__ void storeA(char* smc, int m, int k, float x, float y) {
    uint32_t addr = (uint32_t)(m * 512) + (uint32_t)((((k >> 3) ^ (m & 7)) << 4)) +
                    (uint32_t)((k & 7) * 2);
    *(__half2*)(smc + A_OFF + addr) = __floats2half2_rn(x, y);
}

// ---------------------------------------------------------------------------
// prep: fp16-round w[k][n], write into zero-pad swizzled chunk layout.
// ---------------------------------------------------------------------------
__global__ void prep_weights(const float* __restrict__ w1, const float* __restrict__ w2) {
    int idx = blockIdx.x * blockDim.x + threadIdx.x;   // 131072
    const float* w = (idx < 65536) ? w1 : w2;
    int base = (idx < 65536) ? 0 : 8;
    int i = idx & 65535;
    int k = i >> 8, n = i & 255;
    int chunk = base + (k >> 5);
    int kk = k & 31;
    uint32_t off = (uint32_t)(n * 32) +
                   (uint32_t)((((kk >> 3) ^ ((n >> 1) & 3)) << 3)) + (uint32_t)(kk & 7);
    g_wc[(size_t)chunk * CHUNK_HALFS + off] = __float2half_rn(w[i]);
}

// ---------------------------------------------------------------------------
// Edge kernel: 64 edges/CTA, 128 threads, 2 CTAs/SM.
// Weights streamed via cp.async.bulk (1 instr / 16KB chunk) + mbarrier.
// ---------------------------------------------------------------------------
__global__ __launch_bounds__(128, 2)
void edge_mlp_mma(const float* __restrict__ pos,
                  const int* __restrict__ sup_idx,
                  const int* __restrict__ src_idx,
                  const float* __restrict__ b1,
                  const float* __restrict__ b2) {
    extern __shared__ char smc[];
    const uint32_t sb = smem_u32(smc);
    const int tid  = threadIdx.x;
    const int wid  = tid >> 5;
    const int lane = tid & 31;
    const int mg   = wid & 1;     // rows [mg*32, mg*32+32) = supernode mg
    const int ng   = wid >> 1;    // cols [ng*128, ng*128+128)

    float* b1s = (float*)(smc + B1S_OFF);
    float* b2s = (float*)(smc + B2S_OFF);
    b1s[tid] = b1[tid];       b1s[tid + 128] = b1[tid + 128];
    b2s[tid] = b2[tid];       b2s[tid + 128] = b2[tid + 128];

    // init mbarriers + issue first 4 chunk fills (single thread)
    if (tid == 0) {
        #pragma unroll
        for (int s = 0; s < 4; s++) mbar_init(sb + MBAR_OFF + s * 8, 1);
        asm volatile("fence.proxy.async;" ::: "memory");
        #pragma unroll
        for (int s = 0; s < 4; s++) {
            mbar_expect(sb + MBAR_OFF + s * 8, CHUNK_BYTES);
            bulk_cp(sb + BST_OFF + s * CHUNK_BYTES, g_wc + (size_t)s * CHUNK_HALFS,
                    CHUNK_BYTES, sb + MBAR_OFF + s * 8);
        }
    }

    // ---- relative positions (64 edges) ----
    if (tid < 64) {
        int e = blockIdx.x * 64 + tid;
        int si = sup_idx[e >> 5], sr = src_idx[e];
        float dx = pos[si * 3 + 0] - pos[sr * 3 + 0];
        float dy = pos[si * 3 + 1] - pos[sr * 3 + 1];
        float dz = pos[si * 3 + 2] - pos[sr * 3 + 2];
        float* rb = (float*)(smc + REL_OFF);
        rb[tid * 4 + 0] = dx; rb[tid * 4 + 1] = dy; rb[tid * 4 + 2] = dz;
        rb[tid * 4 + 3] = sqrtf(dx * dx + dy * dy + dz * dz);
    }
    __syncthreads();   // rel + mbarrier init visible

    // ---- sincos embed -> A fp16 (thread: row m=tid&63, half h=tid>>6) ----
    {
        const float* rb = (const float*)(smc + REL_OFF);
        int m = tid & 63, h = tid >> 6;
        float r2 = rb[m * 4 + h * 2], r3 = rb[m * 4 + h * 2 + 1];
        #pragma unroll 4
        for (int j = 0; j < 64; j += 2) {
            int jj = j & 31;
            float om0 = __expf(-(float)jj * OM4_C);
            float om1 = __expf(-(float)(jj + 1) * OM4_C);
            float a0 = r2 * om0, a1 = r2 * om1;
            float c0 = r3 * om0, c1 = r3 * om1;
            if (j < 32) {
                storeA(smc, m, (h * 2) * 64 + j,     __sinf(a0), __sinf(a1));
                storeA(smc, m, (h * 2 + 1) * 64 + j, __sinf(c0), __sinf(c1));
            } else {
                storeA(smc, m, (h * 2) * 64 + j,     __cosf(a0), __cosf(a1));
                storeA(smc, m, (h * 2 + 1) * 64 + j, __cosf(c0), __cosf(c1));
            }
        }
    }
    __syncthreads();   // A ready for all warps

    float acc[2][16][4];
    #pragma unroll
    for (int t = 0; t < 2; t++)
        #pragma unroll
        for (int j = 0; j < 16; j++)
            #pragma unroll
            for (int q = 0; q < 4; q++) acc[t][j][q] = 0.0f;

    // A lane bases: x4 = 16 rows x 2 k-halves
    const uint32_t a_row = (uint32_t)(mg * 32 + (lane & 15));
    const int akh  = (lane >> 4);            // k-half within 16-k step
    const int aswz = lane & 7;               // row swizzle bits (a_row & 7)
    // B lane bases: x4 over an n-tile pair = 16 n-rows x 2 k-halves
    const int bn   = (lane & 7) | (((lane >> 4) & 1) << 3);  // 0..15
    const int bkh  = (lane >> 3) & 1;
    const int gswz = (bn >> 1) & 3;
    const uint32_t bno = (uint32_t)((ng * 128 + bn) * 64);
    const uint32_t boff0 = bno + (uint32_t)(((bkh)     ^ gswz) << 4);  // ks=0
    const uint32_t boff1 = bno + (uint32_t)(((2 + bkh) ^ gswz) << 4);  // ks=1

    const int l4 = lane >> 2;
    const int l2 = (lane & 3) * 2;

    #pragma unroll 1
    for (int c = 0; c < 16; c++) {
        const int slot = c & 3;
        const int kc   = c & 7;
        const int par  = (c >> 2) & 1;

        if (c == 8) {
            // ---- epilogue 1: bias + exact GELU -> rewrite A (fp16) ----
            #pragma unroll
            for (int t = 0; t < 2; t++)
                #pragma unroll
                for (int j = 0; j < 16; j++) {
                    int r  = mg * 32 + t * 16 + l4;
                    int cc = ng * 128 + j * 8 + l2;
                    float v0 = acc[t][j][0] + b1s[cc];
                    float v1 = acc[t][j][1] + b1s[cc + 1];
                    float v2 = acc[t][j][2] + b1s[cc];
                    float v3 = acc[t][j][3] + b1s[cc + 1];
                    v0 = 0.5f * v0 * (1.0f + erff(v0 * 0.70710678f));
                    v1 = 0.5f * v1 * (1.0f + erff(v1 * 0.70710678f));
                    v2 = 0.5f * v2 * (1.0f + erff(v2 * 0.70710678f));
                    v3 = 0.5f * v3 * (1.0f + erff(v3 * 0.70710678f));
                    storeA(smc, r,     cc, v0, v1);
                    storeA(smc, r + 8, cc, v2, v3);
                    acc[t][j][0] = 0.0f; acc[t][j][1] = 0.0f;
                    acc[t][j][2] = 0.0f; acc[t][j][3] = 0.0f;
                }
            __syncthreads();   // H visible to partner warps
        }

        mbar_wait(sb + MBAR_OFF + slot * 8, par);   // chunk data + visibility

        // ---- MMA over this 32-K chunk (2 k-steps of 16) ----
        const uint32_t stg = sb + BST_OFF + (uint32_t)(slot * CHUNK_BYTES);
        #pragma unroll
        for (int ks = 0; ks < 2; ks++) {
            uint32_t ah[2][4];
            const int seg = kc * 4 + ks * 2 + akh;
            const uint32_t aoff = (uint32_t)(((seg ^ aswz) << 4));
            #pragma unroll
            for (int t = 0; t < 2; t++)
                ldm_x4(ah[t], sb + A_OFF + (a_row + (uint32_t)(t * 16)) * 512 + aoff);
            const uint32_t bk = stg + (ks ? boff1 : boff0);
            #pragma unroll
            for (int jp = 0; jp < 8; jp++) {
                uint32_t bh[4];
                ldm_x4(bh, bk + (uint32_t)(jp * 1024));   // 16 n-rows * 64 B
                #pragma unroll
                for (int t = 0; t < 2; t++)
                    #pragma unroll
                    for (int jj = 0; jj < 2; jj++)
                        mma16816(acc[t][jp * 2 + jj], ah[t], bh + jj * 2);
            }
        }

        __syncthreads();   // all warps done with this slot
        if (tid == 0 && c < 12) {
            mbar_expect(sb + MBAR_OFF + slot * 8, CHUNK_BYTES);
            bulk_cp(sb + BST_OFF + slot * CHUNK_BYTES,
                    g_wc + (size_t)(c + 4) * CHUNK_HALFS,
                    CHUNK_BYTES, sb + MBAR_OFF + slot * 8);
        }
    }

    // ---- epilogue 2: bias + mean over supernode (warp-local: 32 rows) ----
    #pragma unroll
    for (int j = 0; j < 16; j++) {
        float s0 = 0.0f, s1 = 0.0f;
        #pragma unroll
        for (int t = 0; t < 2; t++) {
            s0 += acc[t][j][0] + acc[t][j][2];
            s1 += acc[t][j][1] + acc[t][j][3];
        }
        #pragma unroll
        for (int off = 4; off < 32; off <<= 1) {
            s0 += __shfl_xor_sync(0xFFFFFFFFu, s0, off);
            s1 += __shfl_xor_sync(0xFFFFFFFFu, s1, off);
        }
        if (lane < 4) {
            int cc = ng * 128 + j * 8 + lane * 2;
            int s  = blockIdx.x * 2 + mg;
            float2 v;
            v.x = s0 * (1.0f / 32.0f) + b2s[cc];
            v.y = s1 * (1.0f / 32.0f) + b2s[cc + 1];
            *(float2*)&g_agg[(size_t)s * HIDDEN + cc] = v;
        }
    }
}

// ---------------------------------------------------------------------------
// Kernel 2: out = [agg | sincos(sup_pos)] @ wp + bp
// ---------------------------------------------------------------------------
#define BLK_S     64
#define AT_STRIDE 68
#define KCHUNK    32

__global__ __launch_bounds__(256, 1)
void out_proj_kernel(const float* __restrict__ pos,
                     const int* __restrict__ sup_idx,
                     const float* __restrict__ wp, const float* __restrict__ bp,
                     float* __restrict__ out) {
    extern __shared__ float smf[];
    float* At   = smf;
    float* Wb   = At + 512 * AT_STRIDE;
    float* spos = Wb + KCHUNK * 256;

    const int tid = threadIdx.x;
    const int s0  = blockIdx.x * BLK_S;

    #pragma unroll 4
    for (int r = 0; r < BLK_S; r++)
        At[tid * AT_STRIDE + r] = g_agg[(s0 + r) * HIDDEN + tid];

    if (tid < BLK_S) {
        int si = sup_idx[s0 + tid];
        spos[tid * 3 + 0] = pos[si * 3 + 0];
        spos[tid * 3 + 1] = pos[si * 3 + 1];
        spos[tid * 3 + 2] = pos[si * 3 + 2];
    }
    {
        int k = 508 + (tid >> 6);
        int r = tid & 63;
        At[k * AT_STRIDE + r] = 0.0f;
    }
    __syncthreads();

    for (int idx = tid; idx < BLK_S * 252; idx += 256) {
        int r  = idx / 252;
        int kk = idx - r * 252;
        int d  = kk / 84;
        int j  = kk - d * 84;
        int jj = (j < 42) ? j : (j - 42);
        float om = expf(-(float)jj * OM3_C);
        float v  = spos[r * 3 + d] * om;
        At[(256 + kk) * AT_STRIDE + r] = (j < 42) ? sinf(v) : cosf(v);
    }

    const int tx = tid & 31;
    const int ty = tid >> 5;
    const int r0 = ty * 8;

    float biasv[8];
    #pragma unroll
    for (int g = 0; g < 2; g++)
        #pragma unroll
        for (int u = 0; u < 4; u++) biasv[g * 4 + u] = bp[tx * 4 + g * 128 + u];

    float acc[8][8];
    #pragma unroll
    for (int i = 0; i < 8; i++)
        #pragma unroll
        for (int j = 0; j < 8; j++) acc[i][j] = 0.0f;

    for (int kt = 0; kt < 512 / KCHUNK; kt++) {
        __syncthreads();
        {
            const float4* src = (const float4*)(wp + kt * KCHUNK * 256);
            float4* dst = (float4*)Wb;
            #pragma unroll
            for (int i = 0; i < 8; i++) dst[i * 256 + tid] = src[i * 256 + tid];
        }
        __syncthreads();
        #pragma unroll 8
        for (int kk = 0; kk < KCHUNK; kk++) {
            int k = kt * KCHUNK + kk;
            float4 a0 = *(const float4*)&At[k * AT_STRIDE + r0];
            float4 a1 = *(const float4*)&At[k * AT_STRIDE + r0 + 4];
            float a[8] = {a0.x, a0.y, a0.z, a0.w, a1.x, a1.y, a1.z, a1.w};
            float b[8];
            #pragma unroll
            for (int g = 0; g < 2; g++) {
                float4 bb = *(const float4*)&Wb[kk * 256 + tx * 4 + g * 128];
                b[g * 4 + 0] = bb.x; b[g * 4 + 1] = bb.y;
                b[g * 4 + 2] = bb.z; b[g * 4 + 3] = bb.w;
            }
            #pragma unroll
            for (int i = 0; i < 8; i++)
                #pragma unroll
                for (int j = 0; j < 8; j++) acc[i][j] += a[i] * b[j];
        }
    }

    #pragma unroll
    for (int i = 0; i < 8; i++)
        #pragma unroll
        for (int g = 0; g < 2; g++) {
            float4 v;
            v.x = acc[i][g * 4 + 0] + biasv[g * 4 + 0];
            v.y = acc[i][g * 4 + 1] + biasv[g * 4 + 1];
            v.z = acc[i][g * 4 + 2] + biasv[g * 4 + 2];
            v.w = acc[i][g * 4 + 3] + biasv[g * 4 + 3];
            *(float4*)&out[(size_t)(s0 + r0 + i) * HIDDEN + tx * 4 + g * 128] = v;
        }
}

// ---------------------------------------------------------------------------
extern "C" void kernel_launch(void* const* d_in, const int* in_sizes, int n_in,
                              void* d_out, int out_size) {
    const float* pos     = (const float*)d_in[0];
    const int*   sup_idx = (const int*)d_in[1];
    const int*   src_idx = (const int*)d_in[2];
    const float* w1 = (const float*)d_in[4];
    const float* b1 = (const float*)d_in[5];
    const float* w2 = (const float*)d_in[6];
    const float* b2 = (const float*)d_in[7];
    const float* wp = (const float*)d_in[8];
    const float* bp = (const float*)d_in[9];
    float* out = (float*)d_out;

    cudaFuncSetAttribute(edge_mlp_mma,
                         cudaFuncAttributeMaxDynamicSharedMemorySize, SMEM_EDGE);
    const int smem2 = (512 * AT_STRIDE + KCHUNK * 256 + BLK_S * 3) * 4;
    cudaFuncSetAttribute(out_proj_kernel,
                         cudaFuncAttributeMaxDynamicSharedMemorySize, smem2);

    prep_weights<<<512, 256>>>(w1, w2);
    edge_mlp_mma<<<NUM_EDGES / 64, 128, SMEM_EDGE>>>(pos, sup_idx, src_idx, b1, b2);
    out_proj_kernel<<<NUM_SUP / BLK_S, 256, smem2>>>(pos, sup_idx, wp, bp, out);
}